// round 8
// baseline (speedup 1.0000x reference)
#include <cuda_runtime.h>
#include <cuda_bf16.h>
#include <cstdint>

#define N_ 20000
#define E_ 8000
#define F_ 64
#define EPS 1e-10f

#define NPAD 20032          // N_ padded to multiple of 64
#define NCH1 313            // ceil(N_/64)
#define SPLIT1 9
#define CPS1 35             // ceil(313/9)
#define ETILES1 63          // ceil(E_/128)
#define NCH2 125            // E_/64
#define SPLIT2 3
#define CPS2 42             // ceil(125/3)
#define NTILES2 157         // ceil(N_/128)

// gemm1 per-buffer smem layout: P0 8K, P1 8K, Q0 16K, Q1 16K
#define OFF_P0 0
#define OFF_P1 8192
#define OFF_Q0 16384
#define OFF_Q1 32768
#define BUFSTRIDE 49152
#define G1_TOTAL (2 * BUFSTRIDE)   // 98304

// gemm2 (int8) per-buffer: A [128n][128B: h1|h0] 16K, B [64f][128B: x1|x0] 8K
#define G2B_A 0
#define G2B_B 16384
#define G2_BUFSTRIDE 24576
#define G2_TOTAL (2 * G2_BUFSTRIDE)  // 49152

// ---------------- scratch ----------------
__device__ float g_dv[N_];
__device__ float g_de[E_];
__device__ float g_YT[64 * E_];            // Y^T [f][e]
__device__ unsigned short g_XsTh[64 * NPAD];
__device__ unsigned short g_XsTl[64 * NPAD];
__device__ __align__(16) char          g_Y1[64 * E_];  // Yd^T hi digit (s8)
__device__ __align__(16) unsigned char g_Y0[64 * E_];  // Yd^T lo digit (u8)
__device__ float g_c1[64];                 // per-f scale m/32767

// ---------------- helpers ----------------
__device__ __forceinline__ uint32_t smem_u32(const void* p) {
    uint32_t a;
    asm("{ .reg .u64 tmp; cvta.to.shared.u64 tmp, %1; cvt.u32.u64 %0, tmp; }"
        : "=r"(a) : "l"(p));
    return a;
}
#define SW128(o) ((uint32_t)(o) ^ (((uint32_t)(o) >> 3) & 0x70))

__device__ __forceinline__ uint32_t pack2(__nv_bfloat16 a, __nv_bfloat16 b) {
    return (uint32_t)__bfloat16_as_ushort(a) |
           ((uint32_t)__bfloat16_as_ushort(b) << 16);
}
__device__ __forceinline__ void split_bf16(float v, __nv_bfloat16& h, __nv_bfloat16& l) {
    h = __float2bfloat16(v);
    l = __float2bfloat16(v - __bfloat162float(h));
}
__device__ __forceinline__ void cvt_pair(float4 v, uint2& hi, uint2& lo) {
    __nv_bfloat16 h0, l0, h1, l1, h2, l2, h3, l3;
    split_bf16(v.x, h0, l0);
    split_bf16(v.y, h1, l1);
    split_bf16(v.z, h2, l2);
    split_bf16(v.w, h3, l3);
    hi = make_uint2(pack2(h0, h1), pack2(h2, h3));
    lo = make_uint2(pack2(l0, l1), pack2(l2, l3));
}
// H in [0,1) -> 16-bit fixed point digit planes (4 elems packed)
__device__ __forceinline__ void quant_h4(float4 v, uint32_t& d1, uint32_t& d0) {
    uint32_t u0 = __float2uint_rn(v.x * 65536.f); u0 = u0 > 65535u ? 65535u : u0;
    uint32_t u1 = __float2uint_rn(v.y * 65536.f); u1 = u1 > 65535u ? 65535u : u1;
    uint32_t u2 = __float2uint_rn(v.z * 65536.f); u2 = u2 > 65535u ? 65535u : u2;
    uint32_t u3 = __float2uint_rn(v.w * 65536.f); u3 = u3 > 65535u ? 65535u : u3;
    d1 = (u0 >> 8) | ((u1 >> 8) << 8) | ((u2 >> 8) << 16) | ((u3 >> 8) << 24);
    d0 = (u0 & 255u) | ((u1 & 255u) << 8) | ((u2 & 255u) << 16) | ((u3 & 255u) << 24);
}

#define LDMX4(r, addr) \
    asm volatile("ldmatrix.sync.aligned.m8n8.x4.shared.b16 {%0,%1,%2,%3}, [%4];" \
        : "=r"((r)[0]), "=r"((r)[1]), "=r"((r)[2]), "=r"((r)[3]) : "r"(addr))
#define LDMX4T(r, addr) \
    asm volatile("ldmatrix.sync.aligned.m8n8.x4.trans.shared.b16 {%0,%1,%2,%3}, [%4];" \
        : "=r"((r)[0]), "=r"((r)[1]), "=r"((r)[2]), "=r"((r)[3]) : "r"(addr))

__device__ __forceinline__ void mma_bf16(float* c, const uint32_t* a,
                                         uint32_t b0, uint32_t b1) {
    asm volatile(
        "mma.sync.aligned.m16n8k16.row.col.f32.bf16.bf16.f32 "
        "{%0,%1,%2,%3}, {%4,%5,%6,%7}, {%8,%9}, {%0,%1,%2,%3};"
        : "+f"(c[0]), "+f"(c[1]), "+f"(c[2]), "+f"(c[3])
        : "r"(a[0]), "r"(a[1]), "r"(a[2]), "r"(a[3]), "r"(b0), "r"(b1));
}
__device__ __forceinline__ void mma_u8s8(int* c, const uint32_t* a,
                                         uint32_t b0, uint32_t b1) {
    asm volatile(
        "mma.sync.aligned.m16n8k32.row.col.s32.u8.s8.s32 "
        "{%0,%1,%2,%3}, {%4,%5,%6,%7}, {%8,%9}, {%0,%1,%2,%3};"
        : "+r"(c[0]), "+r"(c[1]), "+r"(c[2]), "+r"(c[3])
        : "r"(a[0]), "r"(a[1]), "r"(a[2]), "r"(a[3]), "r"(b0), "r"(b1));
}
__device__ __forceinline__ void mma_u8u8(int* c, const uint32_t* a,
                                         uint32_t b0, uint32_t b1) {
    asm volatile(
        "mma.sync.aligned.m16n8k32.row.col.s32.u8.u8.s32 "
        "{%0,%1,%2,%3}, {%4,%5,%6,%7}, {%8,%9}, {%0,%1,%2,%3};"
        : "+r"(c[0]), "+r"(c[1]), "+r"(c[2]), "+r"(c[3])
        : "r"(a[0]), "r"(a[1]), "r"(a[2]), "r"(a[3]), "r"(b0), "r"(b1));
}

// ---------------- zero scratch (incl. output) ----------------
__global__ void zero_scratch(float* __restrict__ Z) {
    int i = blockIdx.x * blockDim.x + threadIdx.x;
    if (i < N_ * F_) Z[i] = 0.0f;
    if (i < 64 * E_) g_YT[i] = 0.0f;
    if (i < E_) g_de[i] = 0.0f;
}

// ---------------- degrees (one pass over H) ----------------
__global__ void __launch_bounds__(256) degrees_kernel(const float* __restrict__ H) {
    const int t = threadIdx.x;
    const int r0 = blockIdx.x * 46;
    const int r1 = (r0 + 46 < N_) ? r0 + 46 : N_;

    float de_acc[32];
#pragma unroll
    for (int j = 0; j < 32; j++) de_acc[j] = 0.0f;

    __shared__ float wsum[8];

    for (int r = r0; r < r1; r++) {
        const float* __restrict__ row = H + (size_t)r * E_;
        float rs = 0.0f;
#pragma unroll
        for (int j = 0; j < 32; j++) {
            int c = t + 256 * j;
            if (c < E_) {
                float v = row[c];
                rs += v;
                de_acc[j] += v;
            }
        }
#pragma unroll
        for (int off = 16; off > 0; off >>= 1)
            rs += __shfl_down_sync(0xffffffffu, rs, off);
        if ((t & 31) == 0) wsum[t >> 5] = rs;
        __syncthreads();
        if (t == 0) {
            float s = 0.0f;
#pragma unroll
            for (int w = 0; w < 8; w++) s += wsum[w];
            g_dv[r] = s;
        }
        __syncthreads();
    }
#pragma unroll
    for (int j = 0; j < 32; j++) {
        int c = t + 256 * j;
        if (c < E_) atomicAdd(&g_de[c], de_acc[j]);
    }
}

// ---------------- Xs^T materialization (scaled, split bf16, transposed) ------
__global__ void __launch_bounds__(256) scale_x_t(const float* __restrict__ X) {
    __shared__ unsigned short sh[64 * 130];
    __shared__ unsigned short sl[64 * 130];
    const int t = threadIdx.x;
    const int n0 = blockIdx.x * 128;
#pragma unroll
    for (int i = 0; i < 32; i++) {
        int idx = i * 256 + t;
        int nl = idx >> 6, f = idx & 63;
        int n = n0 + nl;
        float v = 0.0f;
        if (n < N_) v = X[(size_t)n * 64 + f] * rsqrtf(g_dv[n] + EPS);
        __nv_bfloat16 h, l;
        split_bf16(v, h, l);
        sh[f * 130 + nl] = __bfloat16_as_ushort(h);
        sl[f * 130 + nl] = __bfloat16_as_ushort(l);
    }
    __syncthreads();
#pragma unroll
    for (int i = 0; i < 32; i++) {
        int idx = i * 256 + t;
        int f = idx >> 7, nl = idx & 127;
        int n = n0 + nl;
        if (n < NPAD) {
            g_XsTh[(size_t)f * NPAD + n] = sh[f * 130 + nl];
            g_XsTl[(size_t)f * NPAD + n] = sl[f * 130 + nl];
        }
    }
}

// ---------------- Yd quantization: per-f max + int8 digit planes ------------
__global__ void __launch_bounds__(256) scale_yq() {
    const int f = blockIdx.x;
    const int t = threadIdx.x;
    const float* __restrict__ yrow = g_YT + (size_t)f * E_;
    __shared__ float wmax[8];
    __shared__ float s_inv;

    float m = 0.0f;
    for (int e = t; e < E_; e += 256) {
        float v = fabsf(yrow[e] * (1.0f / (g_de[e] + EPS)));
        m = fmaxf(m, v);
    }
#pragma unroll
    for (int off = 16; off > 0; off >>= 1)
        m = fmaxf(m, __shfl_down_sync(0xffffffffu, m, off));
    if ((t & 31) == 0) wmax[t >> 5] = m;
    __syncthreads();
    if (t == 0) {
        float bm = 0.0f;
#pragma unroll
        for (int w = 0; w < 8; w++) bm = fmaxf(bm, wmax[w]);
        s_inv = (bm > 0.0f) ? 32767.0f / bm : 0.0f;
        g_c1[f] = bm / 32767.0f;
    }
    __syncthreads();
    const float inv = s_inv;
    for (int e = t; e < E_; e += 256) {
        float v = yrow[e] * (1.0f / (g_de[e] + EPS));
        int q = (int)rintf(v * inv);
        q = q > 32767 ? 32767 : (q < -32767 ? -32767 : q);
        int x1 = q >> 8;      // Euclidean hi digit, fits s8
        int x0 = q & 255;     // lo digit, u8
        g_Y1[(size_t)f * E_ + e] = (char)x1;
        g_Y0[(size_t)f * E_ + e] = (unsigned char)x0;
    }
}

// ============================================================================
// GEMM1: Y^T[64 f, E] += Xs^T[64 f, N] · H[N, E]   (bf16 3-term, unchanged)
// ============================================================================
__device__ __forceinline__ void g1_ks(uint32_t sbo, int ks, int wf, int half,
                                      int ebl, int lane, float acc[2][4][4]) {
    uint32_t ah[2][4], al[2][4];
#pragma unroll
    for (int mt = 0; mt < 2; mt++) {
        int rf = wf * 32 + mt * 16 + (lane & 15);
        uint32_t off = SW128((uint32_t)(rf * 128 + (ks * 16 + (lane >> 4) * 8) * 2));
        LDMX4(ah[mt], sbo + OFF_P0 + off);
        LDMX4(al[mt], sbo + OFF_P1 + off);
    }
#pragma unroll
    for (int pr = 0; pr < 2; pr++) {
        uint32_t bh[4], bl[4];
        int gq = lane >> 3, j = lane & 7;
        int rk = ks * 16 + (gq & 1) * 8 + j;
        int ce = ebl + pr * 16 + (gq >> 1) * 8;
        uint32_t off = SW128((uint32_t)(rk * 128 + ce * 2));
        LDMX4T(bh, sbo + OFF_Q0 + half * 8192 + off);
        LDMX4T(bl, sbo + OFF_Q1 + half * 8192 + off);
#pragma unroll
        for (int mt = 0; mt < 2; mt++)
#pragma unroll
            for (int sub = 0; sub < 2; sub++) {
                float* cc = acc[mt][pr * 2 + sub];
                mma_bf16(cc, ah[mt], bh[sub * 2], bh[sub * 2 + 1]);
                mma_bf16(cc, al[mt], bh[sub * 2], bh[sub * 2 + 1]);
                mma_bf16(cc, ah[mt], bl[sub * 2], bl[sub * 2 + 1]);
            }
    }
}

__device__ __forceinline__ void g1_stsA(char* base, const float4* pa, int i0,
                                        int w, int lane) {
    int hh = lane >> 4;
    int el = (lane & 15) * 4;
#pragma unroll
    for (int i = 0; i < 4; i++) {
        int k = (i0 + i) * 8 + w;
        uint2 hi, lo;
        cvt_pair(pa[i], hi, lo);
        uint32_t off = SW128((uint32_t)(k * 128 + el * 2));
        *(uint2*)(base + OFF_Q0 + hh * 8192 + off) = hi;
        *(uint2*)(base + OFF_Q1 + hh * 8192 + off) = lo;
    }
}

__global__ void __launch_bounds__(256, 2)
gemm1_kernel(const float* __restrict__ H) {
    extern __shared__ char smem[];
    const uint32_t sb = smem_u32(smem);
    const int t = threadIdx.x;
    const int lane = t & 31, w = t >> 5;
    const int e0 = blockIdx.x * 128;
    const int c_begin = blockIdx.y * CPS1;
    int c_end = c_begin + CPS1;
    if (c_end > NCH1) c_end = NCH1;
    const int nch = c_end - c_begin;

    const int wf = w >> 2;
    const int we = w & 3;
    const int half = we >> 1;
    const int ebl = (we & 1) * 32;

    const int eA = e0 + lane * 4;
    const bool eok = (eA < E_);
    const int fB = t >> 2;

    float acc[2][4][4];
#pragma unroll
    for (int a = 0; a < 2; a++)
#pragma unroll
        for (int b = 0; b < 4; b++)
#pragma unroll
            for (int q = 0; q < 4; q++) acc[a][b][q] = 0.0f;

    {
        const int n0 = c_begin * 64;
        float4 pa[8];
#pragma unroll
        for (int i = 0; i < 8; i++) {
            int n = n0 + i * 8 + w;
            pa[i] = (n < N_ && eok) ? *(const float4*)(H + (size_t)n * E_ + eA)
                                    : make_float4(0.f, 0.f, 0.f, 0.f);
        }
        g1_stsA(smem, pa, 0, w, lane);
        g1_stsA(smem, pa + 4, 4, w, lane);
#pragma unroll
        for (int j = 0; j < 2; j++) {
            int sg = (t & 3) + j * 4;
            size_t g = (size_t)fB * NPAD + n0 + sg * 8;
            uint32_t off = SW128((uint32_t)(fB * 128 + sg * 16));
            *(uint4*)(smem + OFF_P0 + off) = *(const uint4*)(g_XsTh + g);
            *(uint4*)(smem + OFF_P1 + off) = *(const uint4*)(g_XsTl + g);
        }
    }
    __syncthreads();

    for (int c = 0; c < nch; c++) {
        const int buf = c & 1;
        const uint32_t sbo = sb + buf * BUFSTRIDE;
        char* nbase = smem + (buf ^ 1) * BUFSTRIDE;
        const bool have = (c + 1 < nch);
        const int n1 = (c_begin + c + 1) * 64;

        uint4 pbh[2], pbl[2];
        if (have) {
#pragma unroll
            for (int j = 0; j < 2; j++) {
                int sg = (t & 3) + j * 4;
                size_t g = (size_t)fB * NPAD + n1 + sg * 8;
                pbh[j] = *(const uint4*)(g_XsTh + g);
                pbl[j] = *(const uint4*)(g_XsTl + g);
            }
        }
        g1_ks(sbo, 0, wf, half, ebl, lane, acc);

        float4 pa1[4];
        if (have) {
#pragma unroll
            for (int i = 0; i < 4; i++) {
                int n = n1 + i * 8 + w;
                pa1[i] = (n < N_ && eok) ? *(const float4*)(H + (size_t)n * E_ + eA)
                                         : make_float4(0.f, 0.f, 0.f, 0.f);
            }
        }
        g1_ks(sbo, 1, wf, half, ebl, lane, acc);

        float4 pa2[4];
        if (have) {
#pragma unroll
            for (int i = 0; i < 4; i++) {
                int n = n1 + (i + 4) * 8 + w;
                pa2[i] = (n < N_ && eok) ? *(const float4*)(H + (size_t)n * E_ + eA)
                                         : make_float4(0.f, 0.f, 0.f, 0.f);
            }
        }
        g1_ks(sbo, 2, wf, half, ebl, lane, acc);
        if (have) g1_stsA(nbase, pa1, 0, w, lane);
        g1_ks(sbo, 3, wf, half, ebl, lane, acc);
        if (have) {
            g1_stsA(nbase, pa2, 4, w, lane);
#pragma unroll
            for (int j = 0; j < 2; j++) {
                int sg = (t & 3) + j * 4;
                uint32_t off = SW128((uint32_t)(fB * 128 + sg * 16));
                *(uint4*)(nbase + OFF_P0 + off) = pbh[j];
                *(uint4*)(nbase + OFF_P1 + off) = pbl[j];
            }
        }
        __syncthreads();
    }

#pragma unroll
    for (int mt = 0; mt < 2; mt++) {
        int f = wf * 32 + mt * 16 + (lane >> 2);
#pragma unroll
        for (int q = 0; q < 4; q++) {
            int e = e0 + we * 32 + q * 8 + (lane & 3) * 2;
            if (e < E_) {
                atomicAdd(&g_YT[(size_t)f * E_ + e], acc[mt][q][0]);
                atomicAdd(&g_YT[(size_t)f * E_ + e + 1], acc[mt][q][1]);
                atomicAdd(&g_YT[(size_t)(f + 8) * E_ + e], acc[mt][q][2]);
                atomicAdd(&g_YT[(size_t)(f + 8) * E_ + e + 1], acc[mt][q][3]);
            }
        }
    }
}

// ============================================================================
// GEMM2 (int8 fixed-point): Z[N,64] += D_v^{-1/2} · H · Yd
// H = (h1*256+h0)/2^16 (u8 planes), Yd = c1_f*(x1*256+x0) with c1=m/32767.
// Sum = c1*(T11 + Tmid/256), T11 = Σh1x1 (u8*s8), Tmid = Σh1x0 + Σh0x1.
// A tile [128n][128B: h1|h0] SW128; B tile [64f][128B: x1|x0] SW128.
// NOTE: lo-plane offset is SW128(x+64) = SW128(x) ^ 64 (NOT +64).
// ============================================================================
__device__ __forceinline__ void g2_kb(uint32_t sbo, int kb, int wn, int wfc,
                                      int lane, int accT[2][4][4],
                                      int accM[2][4][4]) {
    uint32_t a1[2][4], a0[2][4];
#pragma unroll
    for (int mt = 0; mt < 2; mt++) {
        int rn = wn * 32 + mt * 16 + (lane & 15);
        uint32_t off = SW128((uint32_t)(rn * 128 + kb * 32 + (lane >> 4) * 16));
        LDMX4(a1[mt], sbo + G2B_A + off);
        LDMX4(a0[mt], sbo + G2B_A + (off ^ 64));
    }
#pragma unroll
    for (int nt = 0; nt < 2; nt++) {
        uint32_t b1[4], b0[4];
        int fr = wfc * 32 + nt * 16 + (lane >> 4) * 8 + (lane & 7);
        uint32_t off = SW128((uint32_t)(fr * 128 + kb * 32 + ((lane >> 3) & 1) * 16));
        LDMX4(b1, sbo + G2B_B + off);
        LDMX4(b0, sbo + G2B_B + (off ^ 64));
#pragma unroll
        for (int mt = 0; mt < 2; mt++)
#pragma unroll
            for (int sub = 0; sub < 2; sub++) {
                int* cT = accT[mt][nt * 2 + sub];
                int* cM = accM[mt][nt * 2 + sub];
                mma_u8s8(cT, a1[mt], b1[sub * 2], b1[sub * 2 + 1]);
                mma_u8u8(cM, a1[mt], b0[sub * 2], b0[sub * 2 + 1]);
                mma_u8s8(cM, a0[mt], b1[sub * 2], b1[sub * 2 + 1]);
            }
    }
}

// store 4 quantized H rows: r = (i0+i)*16 + t>>4, k-bytes kA..kA+3
__device__ __forceinline__ void g2_stsA(char* base, const uint32_t* d1,
                                        const uint32_t* d0, int i0, int t) {
    int kA = (t & 15) * 4;
#pragma unroll
    for (int i = 0; i < 4; i++) {
        int r = (i0 + i) * 16 + (t >> 4);
        uint32_t off = SW128((uint32_t)(r * 128 + kA));
        *(uint32_t*)(base + G2B_A + off) = d1[i];
        *(uint32_t*)(base + G2B_A + (off ^ 64)) = d0[i];
    }
}

__global__ void __launch_bounds__(256, 2)
gemm2_kernel(const float* __restrict__ H, float* __restrict__ Z) {
    extern __shared__ char smem[];
    const uint32_t sb = smem_u32(smem);
    const int t = threadIdx.x;
    const int lane = t & 31, w = t >> 5;
    const int n0 = blockIdx.x * 128;
    const int c_begin = blockIdx.y * CPS2;
    int c_end = c_begin + CPS2;
    if (c_end > NCH2) c_end = NCH2;
    const int nch = c_end - c_begin;

    const int wn = w >> 1;
    const int wfc = w & 1;
    const int rA = t >> 4;
    const int kA = (t & 15) * 4;
    const int fB = t >> 2;          // B loader: row f, 64B per plane
    const int boB = (t & 3) * 16;

    int accT[2][4][4], accM[2][4][4];
#pragma unroll
    for (int a = 0; a < 2; a++)
#pragma unroll
        for (int b = 0; b < 4; b++)
#pragma unroll
            for (int q = 0; q < 4; q++) { accT[a][b][q] = 0; accM[a][b][q] = 0; }

    // prologue: chunk 0 -> buf 0
    {
        const int k0 = c_begin * 64;
        uint32_t d1[8], d0[8];
#pragma unroll
        for (int i = 0; i < 8; i++) {
            int n = n0 + i * 16 + rA;
            float4 v = (n < N_) ? *(const float4*)(H + (size_t)n * E_ + k0 + kA)
                                : make_float4(0.f, 0.f, 0.f, 0.f);
            quant_h4(v, d1[i], d0[i]);
        }
        g2_stsA(smem, d1, d0, 0, t);
        g2_stsA(smem, d1 + 4, d0 + 4, 4, t);
        {
            size_t g = (size_t)fB * E_ + k0 + boB;
            uint32_t off = SW128((uint32_t)(fB * 128 + boB));
            *(uint4*)(smem + G2B_B + off) = *(const uint4*)(g_Y1 + g);
            *(uint4*)(smem + G2B_B + (off ^ 64)) = *(const uint4*)(g_Y0 + g);
        }
    }
    __syncthreads();

    for (int c = 0; c < nch; c++) {
        const int buf = c & 1;
        const uint32_t sbo = sb + buf * G2_BUFSTRIDE;
        char* nbase = smem + (buf ^ 1) * G2_BUFSTRIDE;
        const bool have = (c + 1 < nch);
        const int k1 = (c_begin + c + 1) * 64;

        uint4 pb1, pb0;
        if (have) {
            size_t g = (size_t)fB * E_ + k1 + boB;
            pb1 = *(const uint4*)(g_Y1 + g);
            pb0 = *(const uint4*)(g_Y0 + g);
        }
        g2_kb(sbo, 0, wn, wfc, lane, accT, accM);

        uint32_t d1[8], d0[8];
        if (have) {
#pragma unroll
            for (int i = 0; i < 8; i++) {
                int n = n0 + i * 16 + rA;
                float4 v = (n < N_) ? *(const float4*)(H + (size_t)n * E_ + k1 + kA)
                                    : make_float4(0.f, 0.f, 0.f, 0.f);
                quant_h4(v, d1[i], d0[i]);
            }
        }
        g2_kb(sbo, 1, wn, wfc, lane, accT, accM);

        if (have) {
            g2_stsA(nbase, d1, d0, 0, t);
            g2_stsA(nbase, d1 + 4, d0 + 4, 4, t);
            uint32_t off = SW128((uint32_t)(fB * 128 + boB));
            *(uint4*)(nbase + G2B_B + off) = pb1;
            *(uint4*)(nbase + G2B_B + (off ^ 64)) = pb0;
        }
        __syncthreads();
    }

    // epilogue: combine digits, scale by c1[f] and rsqrt(d_v), atomic accumulate
#pragma unroll
    for (int mt = 0; mt < 2; mt++) {
        int n_lo = n0 + wn * 32 + mt * 16 + (lane >> 2);
        int n_hi = n_lo + 8;
        float s_lo = (n_lo < N_) ? rsqrtf(g_dv[n_lo] + EPS) : 0.0f;
        float s_hi = (n_hi < N_) ? rsqrtf(g_dv[n_hi] + EPS) : 0.0f;
#pragma unroll
        for (int q = 0; q < 4; q++) {
            int f = wfc * 32 + q * 8 + (lane & 3) * 2;
            float c1a = g_c1[f], c1b = g_c1[f + 1];
            float v0 = c1a * ((float)accT[mt][q][0] + 0.00390625f * (float)accM[mt][q][0]);
            float v1 = c1b * ((float)accT[mt][q][1] + 0.00390625f * (float)accM[mt][q][1]);
            float v2 = c1a * ((float)accT[mt][q][2] + 0.00390625f * (float)accM[mt][q][2]);
            float v3 = c1b * ((float)accT[mt][q][3] + 0.00390625f * (float)accM[mt][q][3]);
            if (n_lo < N_) {
                atomicAdd(&Z[(size_t)n_lo * 64 + f], v0 * s_lo);
                atomicAdd(&Z[(size_t)n_lo * 64 + f + 1], v1 * s_lo);
            }
            if (n_hi < N_) {
                atomicAdd(&Z[(size_t)n_hi * 64 + f], v2 * s_hi);
                atomicAdd(&Z[(size_t)n_hi * 64 + f + 1], v3 * s_hi);
            }
        }
    }
}

// ---------------------------------------------------------------------------
extern "C" void kernel_launch(void* const* d_in, const int* in_sizes, int n_in,
                              void* d_out, int out_size) {
    const float* H = (const float*)d_in[0];  // [N_, E_] fp32
    const float* X = (const float*)d_in[1];  // [N_, F_] fp32
    float* Z = (float*)d_out;                // [N_, F_] fp32

    cudaFuncSetAttribute(gemm1_kernel, cudaFuncAttributeMaxDynamicSharedMemorySize, G1_TOTAL);
    cudaFuncSetAttribute(gemm2_kernel, cudaFuncAttributeMaxDynamicSharedMemorySize, G2_TOTAL);

    zero_scratch<<<(N_ * F_ + 255) / 256, 256>>>(Z);
    degrees_kernel<<<444, 256>>>(H);
    scale_x_t<<<(NPAD + 127) / 128, 256>>>(X);
    gemm1_kernel<<<dim3(ETILES1, SPLIT1), 256, G1_TOTAL>>>(H);
    scale_yq<<<64, 256>>>();
    gemm2_kernel<<<dim3(NTILES2, SPLIT2), 256, G2_TOTAL>>>(H, Z);
}

// round 9
// speedup vs baseline: 1.3787x; 1.3787x over previous
#include <cuda_runtime.h>
#include <cuda_bf16.h>
#include <cstdint>

#define N_ 20000
#define E_ 8000
#define F_ 64
#define EPS 1e-10f

#define NPAD 20032          // N_ padded to multiple of 64
#define TK 32               // K elements per chunk
#define NCH1 626            // NPAD/32
#define SPLIT1 7
#define CPS1 90             // ceil(626/7)
#define ETILES1 63          // ceil(E_/128)
#define NCH2 250            // E_/32
#define SPLIT2 3
#define CPS2 84             // ceil(250/3)
#define NTILES2 157         // ceil(N_/128)

// gemm1 per-stage: P0 4K | P1 4K | Q0 8K | Q1 8K  = 24K  (x2 stages = 48K)
#define G1_P0 0
#define G1_P1 4096
#define G1_Q0 8192
#define G1_Q1 16384
// gemm2 per-stage: A0 8K | A1 8K | B0 4K | B1 4K = 24K
#define G2_A0 0
#define G2_A1 8192
#define G2_B0 16384
#define G2_B1 20480
#define STAGE 24576
#define G_TOTAL (2 * STAGE)   // 49152 per CTA -> 3 CTAs/SM

// ---------------- scratch ----------------
__device__ float g_dv[N_];
__device__ float g_de[E_];
__device__ float g_YT[64 * E_];            // Y^T [f][e]
__device__ unsigned short g_XsTh[64 * NPAD];
__device__ unsigned short g_XsTl[64 * NPAD];
__device__ unsigned short g_YdTh[64 * E_]; // [f][e]
__device__ unsigned short g_YdTl[64 * E_];

// ---------------- helpers ----------------
__device__ __forceinline__ uint32_t smem_u32(const void* p) {
    uint32_t a;
    asm("{ .reg .u64 tmp; cvta.to.shared.u64 tmp, %1; cvt.u32.u64 %0, tmp; }"
        : "=r"(a) : "l"(p));
    return a;
}
#define SW128(o) ((uint32_t)(o) ^ (((uint32_t)(o) >> 3) & 0x70))

// packed sub-rows: 64 logical rows of 64 bytes -> 32 smem rows of 128B
__device__ __forceinline__ uint32_t prow(int f, int kb) {
    return SW128((uint32_t)((f & 31) * 128 + ((f >> 5) << 6) + kb));
}
// 128 logical rows of 64 bytes -> 64 smem rows of 128B
__device__ __forceinline__ uint32_t arow(int n, int kb) {
    return SW128((uint32_t)((n & 63) * 128 + ((n >> 6) << 6) + kb));
}

__device__ __forceinline__ uint32_t pack2(__nv_bfloat16 a, __nv_bfloat16 b) {
    return (uint32_t)__bfloat16_as_ushort(a) |
           ((uint32_t)__bfloat16_as_ushort(b) << 16);
}
__device__ __forceinline__ void split_bf16(float v, __nv_bfloat16& h, __nv_bfloat16& l) {
    h = __float2bfloat16(v);
    l = __float2bfloat16(v - __bfloat162float(h));
}
__device__ __forceinline__ void cvt_pair(float4 v, uint2& hi, uint2& lo) {
    __nv_bfloat16 h0, l0, h1, l1, h2, l2, h3, l3;
    split_bf16(v.x, h0, l0);
    split_bf16(v.y, h1, l1);
    split_bf16(v.z, h2, l2);
    split_bf16(v.w, h3, l3);
    hi = make_uint2(pack2(h0, h1), pack2(h2, h3));
    lo = make_uint2(pack2(l0, l1), pack2(l2, l3));
}

#define LDMX4(r, addr) \
    asm volatile("ldmatrix.sync.aligned.m8n8.x4.shared.b16 {%0,%1,%2,%3}, [%4];" \
        : "=r"((r)[0]), "=r"((r)[1]), "=r"((r)[2]), "=r"((r)[3]) : "r"(addr))
#define LDMX4T(r, addr) \
    asm volatile("ldmatrix.sync.aligned.m8n8.x4.trans.shared.b16 {%0,%1,%2,%3}, [%4];" \
        : "=r"((r)[0]), "=r"((r)[1]), "=r"((r)[2]), "=r"((r)[3]) : "r"(addr))

__device__ __forceinline__ void mma_bf16(float* c, const uint32_t* a,
                                         uint32_t b0, uint32_t b1) {
    asm volatile(
        "mma.sync.aligned.m16n8k16.row.col.f32.bf16.bf16.f32 "
        "{%0,%1,%2,%3}, {%4,%5,%6,%7}, {%8,%9}, {%0,%1,%2,%3};"
        : "+f"(c[0]), "+f"(c[1]), "+f"(c[2]), "+f"(c[3])
        : "r"(a[0]), "r"(a[1]), "r"(a[2]), "r"(a[3]), "r"(b0), "r"(b1));
}

__device__ __forceinline__ void cp_async16(uint32_t dst, const void* src) {
    asm volatile("cp.async.cg.shared.global [%0], [%1], 16;"
                 :: "r"(dst), "l"(src) : "memory");
}
#define CP_COMMIT() asm volatile("cp.async.commit_group;" ::: "memory")
#define CP_WAIT0()  asm volatile("cp.async.wait_group 0;" ::: "memory")

// ---------------- zero scratch (incl. output) ----------------
__global__ void zero_scratch(float* __restrict__ Z) {
    int i = blockIdx.x * blockDim.x + threadIdx.x;
    if (i < N_ * F_) Z[i] = 0.0f;
    if (i < 64 * E_) g_YT[i] = 0.0f;
    if (i < E_) g_de[i] = 0.0f;
}

// ---------------- degrees (one pass over H) ----------------
__global__ void __launch_bounds__(256) degrees_kernel(const float* __restrict__ H) {
    const int t = threadIdx.x;
    const int r0 = blockIdx.x * 46;
    const int r1 = (r0 + 46 < N_) ? r0 + 46 : N_;

    float de_acc[32];
#pragma unroll
    for (int j = 0; j < 32; j++) de_acc[j] = 0.0f;

    __shared__ float wsum[8];

    for (int r = r0; r < r1; r++) {
        const float* __restrict__ row = H + (size_t)r * E_;
        float rs = 0.0f;
#pragma unroll
        for (int j = 0; j < 32; j++) {
            int c = t + 256 * j;
            if (c < E_) {
                float v = row[c];
                rs += v;
                de_acc[j] += v;
            }
        }
#pragma unroll
        for (int off = 16; off > 0; off >>= 1)
            rs += __shfl_down_sync(0xffffffffu, rs, off);
        if ((t & 31) == 0) wsum[t >> 5] = rs;
        __syncthreads();
        if (t == 0) {
            float s = 0.0f;
#pragma unroll
            for (int w = 0; w < 8; w++) s += wsum[w];
            g_dv[r] = s;
        }
        __syncthreads();
    }
#pragma unroll
    for (int j = 0; j < 32; j++) {
        int c = t + 256 * j;
        if (c < E_) atomicAdd(&g_de[c], de_acc[j]);
    }
}

// ---------------- Xs^T materialization (scaled, split bf16, transposed) ------
__global__ void __launch_bounds__(256) scale_x_t(const float* __restrict__ X) {
    __shared__ unsigned short sh[64 * 130];
    __shared__ unsigned short sl[64 * 130];
    const int t = threadIdx.x;
    const int n0 = blockIdx.x * 128;
#pragma unroll
    for (int i = 0; i < 32; i++) {
        int idx = i * 256 + t;
        int nl = idx >> 6, f = idx & 63;
        int n = n0 + nl;
        float v = 0.0f;
        if (n < N_) v = X[(size_t)n * 64 + f] * rsqrtf(g_dv[n] + EPS);
        __nv_bfloat16 h, l;
        split_bf16(v, h, l);
        sh[f * 130 + nl] = __bfloat16_as_ushort(h);
        sl[f * 130 + nl] = __bfloat16_as_ushort(l);
    }
    __syncthreads();
#pragma unroll
    for (int i = 0; i < 32; i++) {
        int idx = i * 256 + t;
        int f = idx >> 7, nl = idx & 127;
        int n = n0 + nl;
        if (n < NPAD) {
            g_XsTh[(size_t)f * NPAD + n] = sh[f * 130 + nl];
            g_XsTl[(size_t)f * NPAD + n] = sl[f * 130 + nl];
        }
    }
}

// ---------------- Yd^T: elementwise scale + split (f-major) ----------------
__global__ void __launch_bounds__(256) scale_y_t() {
    int i = blockIdx.x * blockDim.x + threadIdx.x;
    if (i < 64 * E_) {
        int e = i % E_;
        float v = g_YT[i] * (1.0f / (g_de[e] + EPS));
        __nv_bfloat16 h, l;
        split_bf16(v, h, l);
        g_YdTh[i] = __bfloat16_as_ushort(h);
        g_YdTl[i] = __bfloat16_as_ushort(l);
    }
}

// ============================================================================
// GEMM1: Y^T[64 f, E] += Xs^T[64 f, N] · H[N, E]
// P = XsT planes [64f][32k] (packed 64B rows), Q = H planes (two [32k][64e]
// halves per plane). 3 CTAs/SM.
// ============================================================================
__device__ __forceinline__ void g1_ks(uint32_t sbo, int ks, int wf, int half,
                                      int ebl, int lane, float acc[2][4][4]) {
    uint32_t ah[2][4], al[2][4];
#pragma unroll
    for (int mt = 0; mt < 2; mt++) {
        int rf = wf * 32 + mt * 16 + (lane & 15);
        uint32_t off = prow(rf, (ks * 16 + (lane >> 4) * 8) * 2);
        LDMX4(ah[mt], sbo + G1_P0 + off);
        LDMX4(al[mt], sbo + G1_P1 + off);
    }
#pragma unroll
    for (int pr = 0; pr < 2; pr++) {
        uint32_t bh[4], bl[4];
        int gq = lane >> 3, j = lane & 7;
        int rk = ks * 16 + (gq & 1) * 8 + j;        // 0..31
        int ce = ebl + pr * 16 + (gq >> 1) * 8;
        uint32_t off = (uint32_t)(half * 4096) + SW128((uint32_t)(rk * 128 + ce * 2));
        LDMX4T(bh, sbo + G1_Q0 + off);
        LDMX4T(bl, sbo + G1_Q1 + off);
#pragma unroll
        for (int mt = 0; mt < 2; mt++)
#pragma unroll
            for (int sub = 0; sub < 2; sub++) {
                float* cc = acc[mt][pr * 2 + sub];
                mma_bf16(cc, ah[mt], bh[sub * 2], bh[sub * 2 + 1]);
                mma_bf16(cc, al[mt], bh[sub * 2], bh[sub * 2 + 1]);
                mma_bf16(cc, ah[mt], bl[sub * 2], bl[sub * 2 + 1]);
            }
    }
}

// convert+store 4 H float4s (k = i*8 + w, e-local = lane*4) into Q planes
__device__ __forceinline__ void g1_stsA(char* base, const float4* pa,
                                        int w, int lane) {
    int hh = lane >> 4;
    int el = (lane & 15) * 4;
#pragma unroll
    for (int i = 0; i < 4; i++) {
        int k = i * 8 + w;                          // 0..31
        uint2 hi, lo;
        cvt_pair(pa[i], hi, lo);
        uint32_t off = (uint32_t)(hh * 4096) + SW128((uint32_t)(k * 128 + el * 2));
        *(uint2*)(base + G1_Q0 + off) = hi;
        *(uint2*)(base + G1_Q1 + off) = lo;
    }
}

__global__ void __launch_bounds__(256, 3)
gemm1_kernel(const float* __restrict__ H) {
    extern __shared__ char smem[];
    const uint32_t sb = smem_u32(smem);
    const int t = threadIdx.x;
    const int lane = t & 31, w = t >> 5;
    const int e0 = blockIdx.x * 128;
    const int c_begin = blockIdx.y * CPS1;
    int c_end = c_begin + CPS1;
    if (c_end > NCH1) c_end = NCH1;
    const int nch = c_end - c_begin;

    const int wf = w >> 2;
    const int we = w & 3;
    const int half = we >> 1;
    const int ebl = (we & 1) * 32;

    const int eA = e0 + lane * 4;
    const bool eok = (eA < E_);
    const int fB = t >> 2;
    const int segB = t & 3;

    float acc[2][4][4];
#pragma unroll
    for (int a = 0; a < 2; a++)
#pragma unroll
        for (int b = 0; b < 4; b++)
#pragma unroll
            for (int q = 0; q < 4; q++) acc[a][b][q] = 0.0f;

    // prologue: chunk 0 -> buf 0
    {
        const int n0 = c_begin * TK;
        cp_async16(sb + G1_P0 + prow(fB, segB * 16),
                   g_XsTh + (size_t)fB * NPAD + n0 + segB * 8);
        cp_async16(sb + G1_P1 + prow(fB, segB * 16),
                   g_XsTl + (size_t)fB * NPAD + n0 + segB * 8);
        CP_COMMIT();
        float4 pa[4];
#pragma unroll
        for (int i = 0; i < 4; i++) {
            int n = n0 + i * 8 + w;
            pa[i] = (n < N_ && eok) ? *(const float4*)(H + (size_t)n * E_ + eA)
                                    : make_float4(0.f, 0.f, 0.f, 0.f);
        }
        g1_stsA(smem, pa, w, lane);
        CP_WAIT0();
    }
    __syncthreads();

    for (int c = 0; c < nch; c++) {
        const int buf = c & 1;
        const uint32_t sbo = sb + buf * STAGE;
        char* nbase = smem + (buf ^ 1) * STAGE;
        const uint32_t nsb = sb + (buf ^ 1) * STAGE;
        const bool have = (c + 1 < nch);
        const int n1 = (c_begin + c + 1) * TK;

        if (have) {
            cp_async16(nsb + G1_P0 + prow(fB, segB * 16),
                       g_XsTh + (size_t)fB * NPAD + n1 + segB * 8);
            cp_async16(nsb + G1_P1 + prow(fB, segB * 16),
                       g_XsTl + (size_t)fB * NPAD + n1 + segB * 8);
            CP_COMMIT();
        }
        g1_ks(sbo, 0, wf, half, ebl, lane, acc);

        float4 pa[4];
        if (have) {
#pragma unroll
            for (int i = 0; i < 4; i++) {
                int n = n1 + i * 8 + w;
                pa[i] = (n < N_ && eok) ? *(const float4*)(H + (size_t)n * E_ + eA)
                                        : make_float4(0.f, 0.f, 0.f, 0.f);
            }
        }
        g1_ks(sbo, 1, wf, half, ebl, lane, acc);
        if (have) g1_stsA(nbase, pa, w, lane);
        CP_WAIT0();
        __syncthreads();
    }

    // epilogue: atomic accumulate into g_YT [f][e]
#pragma unroll
    for (int mt = 0; mt < 2; mt++) {
        int f = wf * 32 + mt * 16 + (lane >> 2);
#pragma unroll
        for (int q = 0; q < 4; q++) {
            int e = e0 + we * 32 + q * 8 + (lane & 3) * 2;
            if (e < E_) {
                atomicAdd(&g_YT[(size_t)f * E_ + e], acc[mt][q][0]);
                atomicAdd(&g_YT[(size_t)f * E_ + e + 1], acc[mt][q][1]);
                atomicAdd(&g_YT[(size_t)(f + 8) * E_ + e], acc[mt][q][2]);
                atomicAdd(&g_YT[(size_t)(f + 8) * E_ + e + 1], acc[mt][q][3]);
            }
        }
    }
}

// ============================================================================
// GEMM2: Z[N,64] += D_v^{-1/2} · H[N,E] · Yd  (split-K=3, atomic epilogue)
// A = H planes [128n][32k] (packed 64B rows), B = YdT planes [64f][32k]
// (packed 64B rows). 3 CTAs/SM.
// ============================================================================
__device__ __forceinline__ void g2_ks(uint32_t sbo, int ks, int wn, int wfc,
                                      int lane, float acc[2][4][4]) {
    uint32_t ah[2][4], al[2][4];
#pragma unroll
    for (int mt = 0; mt < 2; mt++) {
        int rn = wn * 32 + mt * 16 + (lane & 15);
        uint32_t off = arow(rn, (ks * 16 + (lane >> 4) * 8) * 2);
        LDMX4(ah[mt], sbo + G2_A0 + off);
        LDMX4(al[mt], sbo + G2_A1 + off);
    }
#pragma unroll
    for (int nt = 0; nt < 2; nt++) {
        uint32_t bh[4], bl[4];
        int fr = wfc * 32 + nt * 16 + (lane >> 4) * 8 + (lane & 7);
        int kb8 = ((lane >> 3) & 1) * 8;
        uint32_t off = prow(fr, (ks * 16 + kb8) * 2);
        LDMX4(bh, sbo + G2_B0 + off);
        LDMX4(bl, sbo + G2_B1 + off);
#pragma unroll
        for (int mt = 0; mt < 2; mt++)
#pragma unroll
            for (int sub = 0; sub < 2; sub++) {
                float* cc = acc[mt][nt * 2 + sub];
                mma_bf16(cc, ah[mt], bh[sub * 2], bh[sub * 2 + 1]);
                mma_bf16(cc, al[mt], bh[sub * 2], bh[sub * 2 + 1]);
                mma_bf16(cc, ah[mt], bl[sub * 2], bl[sub * 2 + 1]);
            }
    }
}

// convert+store 4 H float4s: r = i*32 + (t>>3), k-bytes (t&7)*8
__device__ __forceinline__ void g2_stsA(char* base, const float4* pa, int t) {
    int kb = (t & 7) * 8;
#pragma unroll
    for (int i = 0; i < 4; i++) {
        int r = i * 32 + (t >> 3);
        uint2 hi, lo;
        cvt_pair(pa[i], hi, lo);
        uint32_t off = arow(r, kb);
        *(uint2*)(base + G2_A0 + off) = hi;
        *(uint2*)(base + G2_A1 + off) = lo;
    }
}

__global__ void __launch_bounds__(256, 3)
gemm2_kernel(const float* __restrict__ H, float* __restrict__ Z) {
    extern __shared__ char smem[];
    const uint32_t sb = smem_u32(smem);
    const int t = threadIdx.x;
    const int lane = t & 31, w = t >> 5;
    const int n0 = blockIdx.x * 128;
    const int c_begin = blockIdx.y * CPS2;
    int c_end = c_begin + CPS2;
    if (c_end > NCH2) c_end = NCH2;
    const int nch = c_end - c_begin;

    const int wn = w >> 1;
    const int wfc = w & 1;
    const int rA = t >> 3;          // A loader row sub-index (0..31)
    const int kA = (t & 7) * 4;     // A loader k sub-index
    const int fB = t >> 2;          // B loader: row f
    const int segB = t & 3;

    float acc[2][4][4];
#pragma unroll
    for (int a = 0; a < 2; a++)
#pragma unroll
        for (int b = 0; b < 4; b++)
#pragma unroll
            for (int q = 0; q < 4; q++) acc[a][b][q] = 0.0f;

    // prologue: chunk 0 -> buf 0
    {
        const int k0 = c_begin * TK;
        cp_async16(sb + G2_B0 + prow(fB, segB * 16),
                   g_YdTh + (size_t)fB * E_ + k0 + segB * 8);
        cp_async16(sb + G2_B1 + prow(fB, segB * 16),
                   g_YdTl + (size_t)fB * E_ + k0 + segB * 8);
        CP_COMMIT();
        float4 pa[4];
#pragma unroll
        for (int i = 0; i < 4; i++) {
            int n = n0 + i * 32 + rA;
            pa[i] = (n < N_) ? *(const float4*)(H + (size_t)n * E_ + k0 + kA)
                             : make_float4(0.f, 0.f, 0.f, 0.f);
        }
        g2_stsA(smem, pa, t);
        CP_WAIT0();
    }
    __syncthreads();

    for (int c = 0; c < nch; c++) {
        const int buf = c & 1;
        const uint32_t sbo = sb + buf * STAGE;
        char* nbase = smem + (buf ^ 1) * STAGE;
        const uint32_t nsb = sb + (buf ^ 1) * STAGE;
        const bool have = (c + 1 < nch);
        const int k1 = (c_begin + c + 1) * TK;

        if (have) {
            cp_async16(nsb + G2_B0 + prow(fB, segB * 16),
                       g_YdTh + (size_t)fB * E_ + k1 + segB * 8);
            cp_async16(nsb + G2_B1 + prow(fB, segB * 16),
                       g_YdTl + (size_t)fB * E_ + k1 + segB * 8);
            CP_COMMIT();
        }
        g2_ks(sbo, 0, wn, wfc, lane, acc);

        float4 pa[4];
        if (have) {
#pragma unroll
            for (int i = 0; i < 4; i++) {
                int n = n0 + i * 32 + rA;
                pa[i] = (n < N_) ? *(const float4*)(H + (size_t)n * E_ + k1 + kA)
                                 : make_float4(0.f, 0.f, 0.f, 0.f);
            }
        }
        g2_ks(sbo, 1, wn, wfc, lane, acc);
        if (have) g2_stsA(nbase, pa, t);
        CP_WAIT0();
        __syncthreads();
    }

    // epilogue: scale partials by rsqrt(d_v) and atomically accumulate
#pragma unroll
    for (int mt = 0; mt < 2; mt++) {
        int n_lo = n0 + wn * 32 + mt * 16 + (lane >> 2);
        int n_hi = n_lo + 8;
        float s_lo = (n_lo < N_) ? rsqrtf(g_dv[n_lo] + EPS) : 0.0f;
        float s_hi = (n_hi < N_) ? rsqrtf(g_dv[n_hi] + EPS) : 0.0f;
#pragma unroll
        for (int q = 0; q < 4; q++) {
            int f = wfc * 32 + q * 8 + (lane & 3) * 2;
            if (n_lo < N_) {
                atomicAdd(&Z[(size_t)n_lo * 64 + f], acc[mt][q][0] * s_lo);
                atomicAdd(&Z[(size_t)n_lo * 64 + f + 1], acc[mt][q][1] * s_lo);
            }
            if (n_hi < N_) {
                atomicAdd(&Z[(size_t)n_hi * 64 + f], acc[mt][q][2] * s_hi);
                atomicAdd(&Z[(size_t)n_hi * 64 + f + 1], acc[mt][q][3] * s_hi);
            }
        }
    }
}

// ---------------------------------------------------------------------------
extern "C" void kernel_launch(void* const* d_in, const int* in_sizes, int n_in,
                              void* d_out, int out_size) {
    const float* H = (const float*)d_in[0];  // [N_, E_] fp32
    const float* X = (const float*)d_in[1];  // [N_, F_] fp32
    float* Z = (float*)d_out;                // [N_, F_] fp32

    cudaFuncSetAttribute(gemm1_kernel, cudaFuncAttributeMaxDynamicSharedMemorySize, G_TOTAL);
    cudaFuncSetAttribute(gemm2_kernel, cudaFuncAttributeMaxDynamicSharedMemorySize, G_TOTAL);

    zero_scratch<<<(N_ * F_ + 255) / 256, 256>>>(Z);
    degrees_kernel<<<444, 256>>>(H);
    scale_x_t<<<(NPAD + 127) / 128, 256>>>(X);
    gemm1_kernel<<<dim3(ETILES1, SPLIT1), 256, G_TOTAL>>>(H);
    scale_y_t<<<(64 * E_ + 255) / 256, 256>>>();
    gemm2_kernel<<<dim3(NTILES2, SPLIT2), 256, G_TOTAL>>>(H, Z);
}

// round 10
// speedup vs baseline: 1.6214x; 1.1761x over previous
#include <cuda_runtime.h>
#include <cuda_bf16.h>
#include <cstdint>

#define N_ 20000
#define E_ 8000
#define F_ 64
#define EPS 1e-10f

#define NPAD 20032          // N_ padded to multiple of 64
#define TK 64               // K elements per chunk
#define NCH1 313            // NPAD/64
#define SPLIT1 9
#define CPS1 35             // ceil(313/9)
#define ETILES1 63          // ceil(E_/128)
#define NCH2 125            // E_/64
#define SPLIT2 3
#define CPS2 42             // ceil(125/3)
#define NTILES2 157         // ceil(N_/128)

// gemm1 per-stage: P0 8K | P1 8K | Q0 16K (two 8K e-halves) | Q1 16K
#define G1_P0 0
#define G1_P1 8192
#define G1_Q0 16384
#define G1_Q1 32768
// gemm2 per-stage: A0 16K | A1 16K | B0 8K | B1 8K
#define G2_A0 0
#define G2_A1 16384
#define G2_B0 32768
#define G2_B1 40960
#define STAGE 49152
#define G_TOTAL (2 * STAGE)   // 98304 -> 2 CTAs/SM

// ---------------- scratch ----------------
__device__ float g_dv[N_];
__device__ float g_de[E_];
__device__ float g_YT[64 * E_];            // Y^T [f][e]
__device__ unsigned short g_XsTh[64 * NPAD];
__device__ unsigned short g_XsTl[64 * NPAD];
__device__ unsigned short g_YdTh[64 * E_]; // [f][e]
__device__ unsigned short g_YdTl[64 * E_];

// ---------------- helpers ----------------
__device__ __forceinline__ uint32_t smem_u32(const void* p) {
    uint32_t a;
    asm("{ .reg .u64 tmp; cvta.to.shared.u64 tmp, %1; cvt.u32.u64 %0, tmp; }"
        : "=r"(a) : "l"(p));
    return a;
}
#define SW128(o) ((uint32_t)(o) ^ (((uint32_t)(o) >> 3) & 0x70))

__device__ __forceinline__ uint32_t pack2(__nv_bfloat16 a, __nv_bfloat16 b) {
    return (uint32_t)__bfloat16_as_ushort(a) |
           ((uint32_t)__bfloat16_as_ushort(b) << 16);
}
__device__ __forceinline__ void split_bf16(float v, __nv_bfloat16& h, __nv_bfloat16& l) {
    h = __float2bfloat16(v);
    l = __float2bfloat16(v - __bfloat162float(h));
}
__device__ __forceinline__ void cvt_pair(float4 v, uint2& hi, uint2& lo) {
    __nv_bfloat16 h0, l0, h1, l1, h2, l2, h3, l3;
    split_bf16(v.x, h0, l0);
    split_bf16(v.y, h1, l1);
    split_bf16(v.z, h2, l2);
    split_bf16(v.w, h3, l3);
    hi = make_uint2(pack2(h0, h1), pack2(h2, h3));
    lo = make_uint2(pack2(l0, l1), pack2(l2, l3));
}

#define LDMX4(r, addr) \
    asm volatile("ldmatrix.sync.aligned.m8n8.x4.shared.b16 {%0,%1,%2,%3}, [%4];" \
        : "=r"((r)[0]), "=r"((r)[1]), "=r"((r)[2]), "=r"((r)[3]) : "r"(addr))
#define LDMX4T(r, addr) \
    asm volatile("ldmatrix.sync.aligned.m8n8.x4.trans.shared.b16 {%0,%1,%2,%3}, [%4];" \
        : "=r"((r)[0]), "=r"((r)[1]), "=r"((r)[2]), "=r"((r)[3]) : "r"(addr))

__device__ __forceinline__ void mma_bf16(float* c, const uint32_t* a,
                                         uint32_t b0, uint32_t b1) {
    asm volatile(
        "mma.sync.aligned.m16n8k16.row.col.f32.bf16.bf16.f32 "
        "{%0,%1,%2,%3}, {%4,%5,%6,%7}, {%8,%9}, {%0,%1,%2,%3};"
        : "+f"(c[0]), "+f"(c[1]), "+f"(c[2]), "+f"(c[3])
        : "r"(a[0]), "r"(a[1]), "r"(a[2]), "r"(a[3]), "r"(b0), "r"(b1));
}

__device__ __forceinline__ void cp_async16(uint32_t dst, const void* src) {
    asm volatile("cp.async.cg.shared.global [%0], [%1], 16;"
                 :: "r"(dst), "l"(src) : "memory");
}
#define CP_COMMIT() asm volatile("cp.async.commit_group;" ::: "memory")
#define CP_WAIT0()  asm volatile("cp.async.wait_group 0;" ::: "memory")

// ---------------- zero scratch (incl. output) ----------------
__global__ void zero_scratch(float* __restrict__ Z) {
    int i = blockIdx.x * blockDim.x + threadIdx.x;
    if (i < N_ * F_) Z[i] = 0.0f;
    if (i < 64 * E_) g_YT[i] = 0.0f;
    if (i < E_) g_de[i] = 0.0f;
}

// ---------------- degrees (one pass over H) ----------------
__global__ void __launch_bounds__(256) degrees_kernel(const float* __restrict__ H) {
    const int t = threadIdx.x;
    const int r0 = blockIdx.x * 46;
    const int r1 = (r0 + 46 < N_) ? r0 + 46 : N_;

    float de_acc[32];
#pragma unroll
    for (int j = 0; j < 32; j++) de_acc[j] = 0.0f;

    __shared__ float wsum[8];

    for (int r = r0; r < r1; r++) {
        const float* __restrict__ row = H + (size_t)r * E_;
        float rs = 0.0f;
#pragma unroll
        for (int j = 0; j < 32; j++) {
            int c = t + 256 * j;
            if (c < E_) {
                float v = row[c];
                rs += v;
                de_acc[j] += v;
            }
        }
#pragma unroll
        for (int off = 16; off > 0; off >>= 1)
            rs += __shfl_down_sync(0xffffffffu, rs, off);
        if ((t & 31) == 0) wsum[t >> 5] = rs;
        __syncthreads();
        if (t == 0) {
            float s = 0.0f;
#pragma unroll
            for (int w = 0; w < 8; w++) s += wsum[w];
            g_dv[r] = s;
        }
        __syncthreads();
    }
#pragma unroll
    for (int j = 0; j < 32; j++) {
        int c = t + 256 * j;
        if (c < E_) atomicAdd(&g_de[c], de_acc[j]);
    }
}

// ---------------- Xs^T materialization (scaled, split bf16, transposed) ------
__global__ void __launch_bounds__(256) scale_x_t(const float* __restrict__ X) {
    __shared__ unsigned short sh[64 * 130];
    __shared__ unsigned short sl[64 * 130];
    const int t = threadIdx.x;
    const int n0 = blockIdx.x * 128;
#pragma unroll
    for (int i = 0; i < 32; i++) {
        int idx = i * 256 + t;
        int nl = idx >> 6, f = idx & 63;
        int n = n0 + nl;
        float v = 0.0f;
        if (n < N_) v = X[(size_t)n * 64 + f] * rsqrtf(g_dv[n] + EPS);
        __nv_bfloat16 h, l;
        split_bf16(v, h, l);
        sh[f * 130 + nl] = __bfloat16_as_ushort(h);
        sl[f * 130 + nl] = __bfloat16_as_ushort(l);
    }
    __syncthreads();
#pragma unroll
    for (int i = 0; i < 32; i++) {
        int idx = i * 256 + t;
        int f = idx >> 7, nl = idx & 127;
        int n = n0 + nl;
        if (n < NPAD) {
            g_XsTh[(size_t)f * NPAD + n] = sh[f * 130 + nl];
            g_XsTl[(size_t)f * NPAD + n] = sl[f * 130 + nl];
        }
    }
}

// ---------------- Yd^T: elementwise scale + split (f-major) ----------------
__global__ void __launch_bounds__(256) scale_y_t() {
    int i = blockIdx.x * blockDim.x + threadIdx.x;
    if (i < 64 * E_) {
        int e = i % E_;
        float v = g_YT[i] * (1.0f / (g_de[e] + EPS));
        __nv_bfloat16 h, l;
        split_bf16(v, h, l);
        g_YdTh[i] = __bfloat16_as_ushort(h);
        g_YdTl[i] = __bfloat16_as_ushort(l);
    }
}

// ============================================================================
// GEMM1: Y^T[64 f, E] += Xs^T[64 f, N] · H[N, E]
// 8 warps = 2 k-groups x (2 wf x 2 e-half). Warp tile 32f x 64e, 2 ks each.
// ============================================================================
__global__ void __launch_bounds__(256, 2)
gemm1_kernel(const float* __restrict__ H) {
    extern __shared__ char smem[];
    const uint32_t sb = smem_u32(smem);
    const int t = threadIdx.x;
    const int lane = t & 31, w = t >> 5;
    const int e0 = blockIdx.x * 128;
    const int c_begin = blockIdx.y * CPS1;
    int c_end = c_begin + CPS1;
    if (c_end > NCH1) c_end = NCH1;
    const int nch = c_end - c_begin;

    const int kg = w >> 2;          // ks = kg*2 + {0,1}
    const int wq = w & 3;
    const int wf = wq & 1;          // 32-f slice
    const int half = wq >> 1;       // 64-e half

    // A (P planes) LDSM: addr = sbo + plane + abase + mt*2048 + kpa[p]
    const uint32_t amask = (uint32_t)((lane & 7) << 4);
    const uint32_t abase = (uint32_t)((wf * 32 + (lane & 15)) * 128);
    uint32_t kpa[2];
#pragma unroll
    for (int p = 0; p < 2; p++) {
        int ks = kg * 2 + p;
        kpa[p] = (uint32_t)(ks * 32 + (lane >> 4) * 16) ^ amask;
    }
    // B (Q planes) LDSM: addr = sbo + plane + bbase + ks*2048 + ((pr*32)^m56)
    const int gq = lane >> 3, jj = lane & 7;
    const uint32_t m56 = (uint32_t)((jj << 4) & 96);
    const uint32_t bbase = (uint32_t)(half * 8192 + ((gq & 1) * 8 + jj) * 128 +
                                      (((gq >> 1) * 16) ^ ((jj << 4) & 16)));

    // A loader (H fp32 -> Q planes): rows k=i*8+w, e = e0 + lane*4
    const int eA = e0 + lane * 4;
    const bool eok = (eA < E_);
    const uint32_t qsts = (uint32_t)((lane >> 4) * 8192 +
                          ((w * 128 + (lane & 15) * 8) ^ (w << 4)));
    // B loader cp.async: 2 segs per plane
    const int fB = t >> 2, segB = t & 3;
    const uint32_t psts0 = SW128((uint32_t)(fB * 128 + segB * 16));
    const uint32_t psts1 = SW128((uint32_t)(fB * 128 + (segB + 4) * 16));
    const unsigned short* gXh = g_XsTh + (size_t)fB * NPAD + segB * 8;
    const unsigned short* gXl = g_XsTl + (size_t)fB * NPAD + segB * 8;

    float acc[2][8][4];
#pragma unroll
    for (int a = 0; a < 2; a++)
#pragma unroll
        for (int b = 0; b < 8; b++)
#pragma unroll
            for (int q = 0; q < 4; q++) acc[a][b][q] = 0.0f;

    // prologue: chunk 0 -> buf 0
    {
        const int n0 = c_begin * TK;
        cp_async16(sb + G1_P0 + psts0, gXh + n0);
        cp_async16(sb + G1_P0 + psts1, gXh + n0 + 32);
        cp_async16(sb + G1_P1 + psts0, gXl + n0);
        cp_async16(sb + G1_P1 + psts1, gXl + n0 + 32);
        CP_COMMIT();
#pragma unroll
        for (int g = 0; g < 2; g++) {
            float4 pa[4];
#pragma unroll
            for (int i = 0; i < 4; i++) {
                int n = n0 + (g * 4 + i) * 8 + w;
                pa[i] = (n < N_ && eok) ? *(const float4*)(H + (size_t)n * E_ + eA)
                                        : make_float4(0.f, 0.f, 0.f, 0.f);
            }
#pragma unroll
            for (int i = 0; i < 4; i++) {
                uint2 hi, lo;
                cvt_pair(pa[i], hi, lo);
                uint32_t off = qsts + (uint32_t)((g * 4 + i) * 1024);
                *(uint2*)(smem + G1_Q0 + off) = hi;
                *(uint2*)(smem + G1_Q1 + off) = lo;
            }
        }
        CP_WAIT0();
    }
    __syncthreads();

    for (int c = 0; c < nch; c++) {
        const int buf = c & 1;
        const uint32_t sbo = sb + buf * STAGE;
        char* nbase = smem + (buf ^ 1) * STAGE;
        const uint32_t nsb = sb + (buf ^ 1) * STAGE;
        const bool have = (c + 1 < nch);
        const int n1 = (c_begin + c + 1) * TK;

        if (have) {
            cp_async16(nsb + G1_P0 + psts0, gXh + n1);
            cp_async16(nsb + G1_P0 + psts1, gXh + n1 + 32);
            cp_async16(nsb + G1_P1 + psts0, gXl + n1);
            cp_async16(nsb + G1_P1 + psts1, gXl + n1 + 32);
            CP_COMMIT();
        }

        float4 pa[4];
        if (have) {
#pragma unroll
            for (int i = 0; i < 4; i++) {
                int n = n1 + i * 8 + w;
                pa[i] = (n < N_ && eok) ? *(const float4*)(H + (size_t)n * E_ + eA)
                                        : make_float4(0.f, 0.f, 0.f, 0.f);
            }
        }

        // ---- MMA pass p=0 ----
        {
            uint32_t ah[2][4], al[2][4];
#pragma unroll
            for (int mt = 0; mt < 2; mt++) {
                uint32_t ao = sbo + abase + (uint32_t)(mt * 2048) + kpa[0];
                LDMX4(ah[mt], ao + G1_P0);
                LDMX4(al[mt], ao + G1_P1);
            }
            uint32_t bks = sbo + bbase + (uint32_t)(kg * 2 * 2048);
#pragma unroll
            for (int pr = 0; pr < 4; pr++) {
                uint32_t bh[4], bl[4];
                uint32_t bo = bks + (((uint32_t)(pr * 32)) ^ m56);
                LDMX4T(bh, bo + G1_Q0);
                LDMX4T(bl, bo + G1_Q1);
#pragma unroll
                for (int mt = 0; mt < 2; mt++)
#pragma unroll
                    for (int sub = 0; sub < 2; sub++) {
                        float* cc = acc[mt][pr * 2 + sub];
                        mma_bf16(cc, ah[mt], bh[sub * 2], bh[sub * 2 + 1]);
                        mma_bf16(cc, al[mt], bh[sub * 2], bh[sub * 2 + 1]);
                        mma_bf16(cc, ah[mt], bl[sub * 2], bl[sub * 2 + 1]);
                    }
            }
        }

        if (have) {
#pragma unroll
            for (int i = 0; i < 4; i++) {
                uint2 hi, lo;
                cvt_pair(pa[i], hi, lo);
                uint32_t off = qsts + (uint32_t)(i * 1024);
                *(uint2*)(nbase + G1_Q0 + off) = hi;
                *(uint2*)(nbase + G1_Q1 + off) = lo;
            }
#pragma unroll
            for (int i = 0; i < 4; i++) {
                int n = n1 + (i + 4) * 8 + w;
                pa[i] = (n < N_ && eok) ? *(const float4*)(H + (size_t)n * E_ + eA)
                                        : make_float4(0.f, 0.f, 0.f, 0.f);
            }
        }

        // ---- MMA pass p=1 ----
        {
            uint32_t ah[2][4], al[2][4];
#pragma unroll
            for (int mt = 0; mt < 2; mt++) {
                uint32_t ao = sbo + abase + (uint32_t)(mt * 2048) + kpa[1];
                LDMX4(ah[mt], ao + G1_P0);
                LDMX4(al[mt], ao + G1_P1);
            }
            uint32_t bks = sbo + bbase + (uint32_t)((kg * 2 + 1) * 2048);
#pragma unroll
            for (int pr = 0; pr < 4; pr++) {
                uint32_t bh[4], bl[4];
                uint32_t bo = bks + (((uint32_t)(pr * 32)) ^ m56);
                LDMX4T(bh, bo + G1_Q0);
                LDMX4T(bl, bo + G1_Q1);
#pragma unroll
                for (int mt = 0; mt < 2; mt++)
#pragma unroll
                    for (int sub = 0; sub < 2; sub++) {
                        float* cc = acc[mt][pr * 2 + sub];
                        mma_bf16(cc, ah[mt], bh[sub * 2], bh[sub * 2 + 1]);
                        mma_bf16(cc, al[mt], bh[sub * 2], bh[sub * 2 + 1]);
                        mma_bf16(cc, ah[mt], bl[sub * 2], bl[sub * 2 + 1]);
                    }
            }
        }

        if (have) {
#pragma unroll
            for (int i = 0; i < 4; i++) {
                uint2 hi, lo;
                cvt_pair(pa[i], hi, lo);
                uint32_t off = qsts + (uint32_t)((i + 4) * 1024);
                *(uint2*)(nbase + G1_Q0 + off) = hi;
                *(uint2*)(nbase + G1_Q1 + off) = lo;
            }
        }
        CP_WAIT0();
        __syncthreads();
    }

    // epilogue: atomic accumulate into g_YT [f][e] (both k-groups add)
#pragma unroll
    for (int mt = 0; mt < 2; mt++) {
        int f = wf * 32 + mt * 16 + (lane >> 2);
#pragma unroll
        for (int q = 0; q < 8; q++) {
            int e = e0 + half * 64 + q * 8 + (lane & 3) * 2;
            if (e < E_) {
                atomicAdd(&g_YT[(size_t)f * E_ + e], acc[mt][q][0]);
                atomicAdd(&g_YT[(size_t)f * E_ + e + 1], acc[mt][q][1]);
                atomicAdd(&g_YT[(size_t)(f + 8) * E_ + e], acc[mt][q][2]);
                atomicAdd(&g_YT[(size_t)(f + 8) * E_ + e + 1], acc[mt][q][3]);
            }
        }
    }
}

// ============================================================================
// GEMM2: Z[N,64] += D_v^{-1/2} · H[N,E] · Yd
// 8 warps = 2 k-groups x (2 wn x 2 wfc). Warp tile 64n x 32f, 2 ks each.
// ============================================================================
__global__ void __launch_bounds__(256, 2)
gemm2_kernel(const float* __restrict__ H, float* __restrict__ Z) {
    extern __shared__ char smem[];
    const uint32_t sb = smem_u32(smem);
    const int t = threadIdx.x;
    const int lane = t & 31, w = t >> 5;
    const int n0 = blockIdx.x * 128;
    const int c_begin = blockIdx.y * CPS2;
    int c_end = c_begin + CPS2;
    if (c_end > NCH2) c_end = NCH2;
    const int nch = c_end - c_begin;

    const int kg = w >> 2;
    const int wq = w & 3;
    const int wn = wq >> 1;         // 64-n half
    const int wfc = wq & 1;         // 32-f slice

    // A LDSM: addr = sbo + plane + a2base + mt*2048 + kpa[p]
    const uint32_t amask = (uint32_t)((lane & 7) << 4);
    const uint32_t a2base = (uint32_t)((wn * 64 + (lane & 15)) * 128);
    uint32_t kpa[2];
#pragma unroll
    for (int p = 0; p < 2; p++) {
        int ks = kg * 2 + p;
        kpa[p] = (uint32_t)(ks * 32 + (lane >> 4) * 16) ^ amask;
    }
    // B LDSM: addr = sbo + plane + b2base + nt*2048 + kpb[p]
    const uint32_t b2base = (uint32_t)((wfc * 32 + (lane >> 4) * 8 + (lane & 7)) * 128);
    uint32_t kpb[2];
#pragma unroll
    for (int p = 0; p < 2; p++) {
        int ks = kg * 2 + p;
        kpb[p] = (uint32_t)(ks * 32 + ((lane >> 3) & 1) * 16) ^ amask;
    }

    // A loader (H fp32 -> A planes): rows it*16 + rb, k-col (lane&15)*4
    const int rb = w * 2 + (lane >> 4);
    const int kA = (lane & 15) * 4;
    const uint32_t a2sts = (uint32_t)(rb * 128 + (((lane & 15) * 8) ^ ((rb & 7) << 4)));
    // B loader cp.async
    const int fB = t >> 2, segB = t & 3;
    const uint32_t psts0 = SW128((uint32_t)(fB * 128 + segB * 16));
    const uint32_t psts1 = SW128((uint32_t)(fB * 128 + (segB + 4) * 16));
    const unsigned short* gYh = g_YdTh + (size_t)fB * E_ + segB * 8;
    const unsigned short* gYl = g_YdTl + (size_t)fB * E_ + segB * 8;

    float acc[4][4][4];
#pragma unroll
    for (int a = 0; a < 4; a++)
#pragma unroll
        for (int b = 0; b < 4; b++)
#pragma unroll
            for (int q = 0; q < 4; q++) acc[a][b][q] = 0.0f;

    // prologue: chunk 0 -> buf 0
    {
        const int k0 = c_begin * TK;
        cp_async16(sb + G2_B0 + psts0, gYh + k0);
        cp_async16(sb + G2_B0 + psts1, gYh + k0 + 32);
        cp_async16(sb + G2_B1 + psts0, gYl + k0);
        cp_async16(sb + G2_B1 + psts1, gYl + k0 + 32);
        CP_COMMIT();
#pragma unroll
        for (int g = 0; g < 2; g++) {
            float4 pa[4];
#pragma unroll
            for (int i = 0; i < 4; i++) {
                int n = n0 + (g * 4 + i) * 16 + rb;
                pa[i] = (n < N_) ? *(const float4*)(H + (size_t)n * E_ + k0 + kA)
                                 : make_float4(0.f, 0.f, 0.f, 0.f);
            }
#pragma unroll
            for (int i = 0; i < 4; i++) {
                uint2 hi, lo;
                cvt_pair(pa[i], hi, lo);
                uint32_t off = a2sts + (uint32_t)((g * 4 + i) * 2048);
                *(uint2*)(smem + G2_A0 + off) = hi;
                *(uint2*)(smem + G2_A1 + off) = lo;
            }
        }
        CP_WAIT0();
    }
    __syncthreads();

    for (int c = 0; c < nch; c++) {
        const int buf = c & 1;
        const uint32_t sbo = sb + buf * STAGE;
        char* nbase = smem + (buf ^ 1) * STAGE;
        const uint32_t nsb = sb + (buf ^ 1) * STAGE;
        const bool have = (c + 1 < nch);
        const int k1 = (c_begin + c + 1) * TK;

        if (have) {
            cp_async16(nsb + G2_B0 + psts0, gYh + k1);
            cp_async16(nsb + G2_B0 + psts1, gYh + k1 + 32);
            cp_async16(nsb + G2_B1 + psts0, gYl + k1);
            cp_async16(nsb + G2_B1 + psts1, gYl + k1 + 32);
            CP_COMMIT();
        }

        float4 pa[4];
        if (have) {
#pragma unroll
            for (int i = 0; i < 4; i++) {
                int n = n0 + i * 16 + rb;
                pa[i] = (n < N_) ? *(const float4*)(H + (size_t)n * E_ + k1 + kA)
                                 : make_float4(0.f, 0.f, 0.f, 0.f);
            }
        }

        // ---- MMA pass p=0 ----
        {
            uint32_t bh[2][4], bl[2][4];
#pragma unroll
            for (int nt = 0; nt < 2; nt++) {
                uint32_t bo = sbo + b2base + (uint32_t)(nt * 2048) + kpb[0];
                LDMX4(bh[nt], bo + G2_B0);
                LDMX4(bl[nt], bo + G2_B1);
            }
#pragma unroll
            for (int mg = 0; mg < 2; mg++) {
                uint32_t ah[2][4], al[2][4];
#pragma unroll
                for (int mi = 0; mi < 2; mi++) {
                    uint32_t ao = sbo + a2base + (uint32_t)((mg * 2 + mi) * 2048) + kpa[0];
                    LDMX4(ah[mi], ao + G2_A0);
                    LDMX4(al[mi], ao + G2_A1);
                }
#pragma unroll
                for (int mi = 0; mi < 2; mi++)
#pragma unroll
                    for (int nt = 0; nt < 2; nt++)
#pragma unroll
                        for (int sub = 0; sub < 2; sub++) {
                            float* cc = acc[mg * 2 + mi][nt * 2 + sub];
                            mma_bf16(cc, ah[mi], bh[nt][sub * 2], bh[nt][sub * 2 + 1]);
                            mma_bf16(cc, al[mi], bh[nt][sub * 2], bh[nt][sub * 2 + 1]);
                            mma_bf16(cc, ah[mi], bl[nt][sub * 2], bl[nt][sub * 2 + 1]);
                        }
            }
        }

        if (have) {
#pragma unroll
            for (int i = 0; i < 4; i++) {
                uint2 hi, lo;
                cvt_pair(pa[i], hi, lo);
                uint32_t off = a2sts + (uint32_t)(i * 2048);
                *(uint2*)(nbase + G2_A0 + off) = hi;
                *(uint2*)(nbase + G2_A1 + off) = lo;
            }
#pragma unroll
            for (int i = 0; i < 4; i++) {
                int n = n0 + (i + 4) * 16 + rb;
                pa[i] = (n < N_) ? *(const float4*)(H + (size_t)n * E_ + k1 + kA)
                                 : make_float4(0.f, 0.f, 0.f, 0.f);
            }
        }

        // ---- MMA pass p=1 ----
        {
            uint32_t bh[2][4], bl[2][4];
#pragma unroll
            for (int nt = 0; nt < 2; nt++) {
                uint32_t bo = sbo + b2base + (uint32_t)(nt * 2048) + kpb[1];
                LDMX4(bh[nt], bo + G2_B0);
                LDMX4(bl[nt], bo + G2_B1);
            }
#pragma unroll
            for (int mg = 0; mg < 2; mg++) {
                uint32_t ah[2][4], al[2][4];
#pragma unroll
                for (int mi = 0; mi < 2; mi++) {
                    uint32_t ao = sbo + a2base + (uint32_t)((mg * 2 + mi) * 2048) + kpa[1];
                    LDMX4(ah[mi], ao + G2_A0);
                    LDMX4(al[mi], ao + G2_A1);
                }
#pragma unroll
                for (int mi = 0; mi < 2; mi++)
#pragma unroll
                    for (int nt = 0; nt < 2; nt++)
#pragma unroll
                        for (int sub = 0; sub < 2; sub++) {
                            float* cc = acc[mg * 2 + mi][nt * 2 + sub];
                            mma_bf16(cc, ah[mi], bh[nt][sub * 2], bh[nt][sub * 2 + 1]);
                            mma_bf16(cc, al[mi], bh[nt][sub * 2], bh[nt][sub * 2 + 1]);
                            mma_bf16(cc, ah[mi], bl[nt][sub * 2], bl[nt][sub * 2 + 1]);
                        }
            }
        }

        if (have) {
#pragma unroll
            for (int i = 0; i < 4; i++) {
                uint2 hi, lo;
                cvt_pair(pa[i], hi, lo);
                uint32_t off = a2sts + (uint32_t)((i + 4) * 2048);
                *(uint2*)(nbase + G2_A0 + off) = hi;
                *(uint2*)(nbase + G2_A1 + off) = lo;
            }
        }
        CP_WAIT0();
        __syncthreads();
    }

    // epilogue: scale partials by rsqrt(d_v) and atomically accumulate
#pragma unroll
    for (int mt = 0; mt < 4; mt++) {
        int n_lo = n0 + wn * 64 + mt * 16 + (lane >> 2);
        int n_hi = n_lo + 8;
        float s_lo = (n_lo < N_) ? rsqrtf(g_dv[n_lo] + EPS) : 0.0f;
        float s_hi = (n_hi < N_) ? rsqrtf(g_dv[n_hi] + EPS) : 0.0f;
#pragma unroll
        for (int q = 0; q < 4; q++) {
            int f = wfc * 32 + q * 8 + (lane & 3) * 2;
            if (n_lo < N_) {
                atomicAdd(&Z[(size_t)n_lo * 64 + f], acc[mt][q][0] * s_lo);
                atomicAdd(&Z[(size_t)n_lo * 64 + f + 1], acc[mt][q][1] * s_lo);
            }
            if (n_hi < N_) {
                atomicAdd(&Z[(size_t)n_hi * 64 + f], acc[mt][q][2] * s_hi);
                atomicAdd(&Z[(size_t)n_hi * 64 + f + 1], acc[mt][q][3] * s_hi);
            }
        }
    }
}

// ---------------------------------------------------------------------------
extern "C" void kernel_launch(void* const* d_in, const int* in_sizes, int n_in,
                              void* d_out, int out_size) {
    const float* H = (const float*)d_in[0];  // [N_, E_] fp32
    const float* X = (const float*)d_in[1];  // [N_, F_] fp32
    float* Z = (float*)d_out;                // [N_, F_] fp32

    cudaFuncSetAttribute(gemm1_kernel, cudaFuncAttributeMaxDynamicSharedMemorySize, G_TOTAL);
    cudaFuncSetAttribute(gemm2_kernel, cudaFuncAttributeMaxDynamicSharedMemorySize, G_TOTAL);

    zero_scratch<<<(N_ * F_ + 255) / 256, 256>>>(Z);
    degrees_kernel<<<444, 256>>>(H);
    scale_x_t<<<(NPAD + 127) / 128, 256>>>(X);
    gemm1_kernel<<<dim3(ETILES1, SPLIT1), 256, G_TOTAL>>>(H);
    scale_y_t<<<(64 * E_ + 255) / 256, 256>>>();
    gemm2_kernel<<<dim3(NTILES2, SPLIT2), 256, G_TOTAL>>>(H, Z);
}

// round 12
// speedup vs baseline: 1.6387x; 1.0107x over previous
#include <cuda_runtime.h>
#include <cuda_bf16.h>
#include <cstdint>

#define N_ 20000
#define E_ 8000
#define F_ 64
#define EPS 1e-10f

#define NPAD 20032          // N_ padded to multiple of 64
#define TK 64               // K elements per chunk
#define NCH1 313            // NPAD/64
#define SPLIT1 9
#define CPS1 35             // ceil(313/9)
#define ETILES1 63          // ceil(E_/128)
#define NCH2 125            // E_/64
#define SPLIT2 3
#define CPS2 42             // ceil(125/3)
#define NTILES2 157         // ceil(N_/128)

// gemm1 per-stage: P0 8K | P1 8K | Q0 16K (two 8K e-halves) | Q1 16K
#define G1_P0 0
#define G1_P1 8192
#define G1_Q0 16384
#define G1_Q1 32768
// gemm2 per-stage: A0 16K | A1 16K | B0 8K | B1 8K
#define G2_A0 0
#define G2_A1 16384
#define G2_B0 32768
#define G2_B1 40960
#define STAGE 49152
#define G_TOTAL (2 * STAGE)   // 98304 -> 2 CTAs/SM

// ---------------- scratch ----------------
__device__ float g_dv[N_];
__device__ float g_de[E_];
__device__ float g_YT[64 * E_];            // Y^T [f][e]
__device__ unsigned short g_XsTh[64 * NPAD];
__device__ unsigned short g_XsTl[64 * NPAD];
__device__ unsigned short g_YdTh[64 * E_]; // [f][e]
__device__ unsigned short g_YdTl[64 * E_];

// ---------------- helpers ----------------
__device__ __forceinline__ uint32_t smem_u32(const void* p) {
    uint32_t a;
    asm("{ .reg .u64 tmp; cvta.to.shared.u64 tmp, %1; cvt.u32.u64 %0, tmp; }"
        : "=r"(a) : "l"(p));
    return a;
}
#define SW128(o) ((uint32_t)(o) ^ (((uint32_t)(o) >> 3) & 0x70))

__device__ __forceinline__ uint32_t pack2(__nv_bfloat16 a, __nv_bfloat16 b) {
    return (uint32_t)__bfloat16_as_ushort(a) |
           ((uint32_t)__bfloat16_as_ushort(b) << 16);
}
__device__ __forceinline__ void split_bf16(float v, __nv_bfloat16& h, __nv_bfloat16& l) {
    h = __float2bfloat16(v);
    l = __float2bfloat16(v - __bfloat162float(h));
}
__device__ __forceinline__ void cvt_pair(float4 v, uint2& hi, uint2& lo) {
    __nv_bfloat16 h0, l0, h1, l1, h2, l2, h3, l3;
    split_bf16(v.x, h0, l0);
    split_bf16(v.y, h1, l1);
    split_bf16(v.z, h2, l2);
    split_bf16(v.w, h3, l3);
    hi = make_uint2(pack2(h0, h1), pack2(h2, h3));
    lo = make_uint2(pack2(l0, l1), pack2(l2, l3));
}

#define LDMX4(r, addr) \
    asm volatile("ldmatrix.sync.aligned.m8n8.x4.shared.b16 {%0,%1,%2,%3}, [%4];" \
        : "=r"((r)[0]), "=r"((r)[1]), "=r"((r)[2]), "=r"((r)[3]) : "r"(addr))
#define LDMX4T(r, addr) \
    asm volatile("ldmatrix.sync.aligned.m8n8.x4.trans.shared.b16 {%0,%1,%2,%3}, [%4];" \
        : "=r"((r)[0]), "=r"((r)[1]), "=r"((r)[2]), "=r"((r)[3]) : "r"(addr))

__device__ __forceinline__ void mma_bf16(float* c, const uint32_t* a,
                                         uint32_t b0, uint32_t b1) {
    asm volatile(
        "mma.sync.aligned.m16n8k16.row.col.f32.bf16.bf16.f32 "
        "{%0,%1,%2,%3}, {%4,%5,%6,%7}, {%8,%9}, {%0,%1,%2,%3};"
        : "+f"(c[0]), "+f"(c[1]), "+f"(c[2]), "+f"(c[3])
        : "r"(a[0]), "r"(a[1]), "r"(a[2]), "r"(a[3]), "r"(b0), "r"(b1));
}

__device__ __forceinline__ void cp_async16(uint32_t dst, const void* src) {
    asm volatile("cp.async.cg.shared.global [%0], [%1], 16;"
                 :: "r"(dst), "l"(src) : "memory");
}
#define CP_COMMIT() asm volatile("cp.async.commit_group;" ::: "memory")
#define CP_WAIT0()  asm volatile("cp.async.wait_group 0;" ::: "memory")

// ---------------- zero scratch (incl. output) ----------------
__global__ void zero_scratch(float* __restrict__ Z) {
    int i = blockIdx.x * blockDim.x + threadIdx.x;
    if (i < N_ * F_) Z[i] = 0.0f;
    if (i < 64 * E_) g_YT[i] = 0.0f;
    if (i < E_) g_de[i] = 0.0f;
}

// ---------------- degrees (one pass over H) ----------------
__global__ void __launch_bounds__(256) degrees_kernel(const float* __restrict__ H) {
    const int t = threadIdx.x;
    const int r0 = blockIdx.x * 46;
    const int r1 = (r0 + 46 < N_) ? r0 + 46 : N_;

    float de_acc[32];
#pragma unroll
    for (int j = 0; j < 32; j++) de_acc[j] = 0.0f;

    __shared__ float wsum[8];

    for (int r = r0; r < r1; r++) {
        const float* __restrict__ row = H + (size_t)r * E_;
        float rs = 0.0f;
#pragma unroll
        for (int j = 0; j < 32; j++) {
            int c = t + 256 * j;
            if (c < E_) {
                float v = row[c];
                rs += v;
                de_acc[j] += v;
            }
        }
#pragma unroll
        for (int off = 16; off > 0; off >>= 1)
            rs += __shfl_down_sync(0xffffffffu, rs, off);
        if ((t & 31) == 0) wsum[t >> 5] = rs;
        __syncthreads();
        if (t == 0) {
            float s = 0.0f;
#pragma unroll
            for (int w = 0; w < 8; w++) s += wsum[w];
            g_dv[r] = s;
        }
        __syncthreads();
    }
#pragma unroll
    for (int j = 0; j < 32; j++) {
        int c = t + 256 * j;
        if (c < E_) atomicAdd(&g_de[c], de_acc[j]);
    }
}

// ---------------- Xs^T materialization (scaled, split bf16, transposed) ------
__global__ void __launch_bounds__(256) scale_x_t(const float* __restrict__ X) {
    __shared__ unsigned short sh[64 * 130];
    __shared__ unsigned short sl[64 * 130];
    const int t = threadIdx.x;
    const int n0 = blockIdx.x * 128;
#pragma unroll
    for (int i = 0; i < 32; i++) {
        int idx = i * 256 + t;
        int nl = idx >> 6, f = idx & 63;
        int n = n0 + nl;
        float v = 0.0f;
        if (n < N_) v = X[(size_t)n * 64 + f] * rsqrtf(g_dv[n] + EPS);
        __nv_bfloat16 h, l;
        split_bf16(v, h, l);
        sh[f * 130 + nl] = __bfloat16_as_ushort(h);
        sl[f * 130 + nl] = __bfloat16_as_ushort(l);
    }
    __syncthreads();
#pragma unroll
    for (int i = 0; i < 32; i++) {
        int idx = i * 256 + t;
        int f = idx >> 7, nl = idx & 127;
        int n = n0 + nl;
        if (n < NPAD) {
            g_XsTh[(size_t)f * NPAD + n] = sh[f * 130 + nl];
            g_XsTl[(size_t)f * NPAD + n] = sl[f * 130 + nl];
        }
    }
}

// ---------------- Yd^T: elementwise scale + split (f-major) ----------------
__global__ void __launch_bounds__(256) scale_y_t() {
    int i = blockIdx.x * blockDim.x + threadIdx.x;
    if (i < 64 * E_) {
        int e = i % E_;
        float v = g_YT[i] * (1.0f / (g_de[e] + EPS));
        __nv_bfloat16 h, l;
        split_bf16(v, h, l);
        g_YdTh[i] = __bfloat16_as_ushort(h);
        g_YdTl[i] = __bfloat16_as_ushort(l);
    }
}

// ============================================================================
// GEMM1: Y^T[64 f, E] += Xs^T[64 f, N] · H[N, E]
// 8 warps = 2 k-groups x (2 wf x 2 e-half). Warp tile 32f x 64e, 2 ks each.
// Term-major MMA ordering: same-acc reuse distance 8.
// ============================================================================
__global__ void __launch_bounds__(256, 2)
gemm1_kernel(const float* __restrict__ H) {
    extern __shared__ char smem[];
    const uint32_t sb = smem_u32(smem);
    const int t = threadIdx.x;
    const int lane = t & 31, w = t >> 5;
    const int e0 = blockIdx.x * 128;
    const int c_begin = blockIdx.y * CPS1;
    int c_end = c_begin + CPS1;
    if (c_end > NCH1) c_end = NCH1;
    const int nch = c_end - c_begin;

    const int kg = w >> 2;          // ks = kg*2 + {0,1}
    const int wq = w & 3;
    const int wf = wq & 1;          // 32-f slice
    const int half = wq >> 1;       // 64-e half

    const uint32_t amask = (uint32_t)((lane & 7) << 4);
    const uint32_t abase = (uint32_t)((wf * 32 + (lane & 15)) * 128);
    uint32_t kpa[2];
#pragma unroll
    for (int p = 0; p < 2; p++) {
        int ks = kg * 2 + p;
        kpa[p] = (uint32_t)(ks * 32 + (lane >> 4) * 16) ^ amask;
    }
    const int gq = lane >> 3, jj = lane & 7;
    const uint32_t m56 = (uint32_t)((jj << 4) & 96);
    const uint32_t bbase = (uint32_t)(half * 8192 + ((gq & 1) * 8 + jj) * 128 +
                                      (((gq >> 1) * 16) ^ ((jj << 4) & 16)));

    const int eA = e0 + lane * 4;
    const bool eok = (eA < E_);
    const uint32_t qsts = (uint32_t)((lane >> 4) * 8192 +
                          ((w * 128 + (lane & 15) * 8) ^ (w << 4)));
    const int fB = t >> 2, segB = t & 3;
    const uint32_t psts0 = SW128((uint32_t)(fB * 128 + segB * 16));
    const uint32_t psts1 = SW128((uint32_t)(fB * 128 + (segB + 4) * 16));
    const unsigned short* gXh = g_XsTh + (size_t)fB * NPAD + segB * 8;
    const unsigned short* gXl = g_XsTl + (size_t)fB * NPAD + segB * 8;

    float acc[2][8][4];
#pragma unroll
    for (int a = 0; a < 2; a++)
#pragma unroll
        for (int b = 0; b < 8; b++)
#pragma unroll
            for (int q = 0; q < 4; q++) acc[a][b][q] = 0.0f;

    // prologue: chunk 0 -> buf 0
    {
        const int n0 = c_begin * TK;
        cp_async16(sb + G1_P0 + psts0, gXh + n0);
        cp_async16(sb + G1_P0 + psts1, gXh + n0 + 32);
        cp_async16(sb + G1_P1 + psts0, gXl + n0);
        cp_async16(sb + G1_P1 + psts1, gXl + n0 + 32);
        CP_COMMIT();
#pragma unroll
        for (int g = 0; g < 2; g++) {
            float4 pa[4];
#pragma unroll
            for (int i = 0; i < 4; i++) {
                int n = n0 + (g * 4 + i) * 8 + w;
                pa[i] = (n < N_ && eok) ? *(const float4*)(H + (size_t)n * E_ + eA)
                                        : make_float4(0.f, 0.f, 0.f, 0.f);
            }
#pragma unroll
            for (int i = 0; i < 4; i++) {
                uint2 hi, lo;
                cvt_pair(pa[i], hi, lo);
                uint32_t off = qsts + (uint32_t)((g * 4 + i) * 1024);
                *(uint2*)(smem + G1_Q0 + off) = hi;
                *(uint2*)(smem + G1_Q1 + off) = lo;
            }
        }
        CP_WAIT0();
    }
    __syncthreads();

    for (int c = 0; c < nch; c++) {
        const int buf = c & 1;
        const uint32_t sbo = sb + buf * STAGE;
        char* nbase = smem + (buf ^ 1) * STAGE;
        const uint32_t nsb = sb + (buf ^ 1) * STAGE;
        const bool have = (c + 1 < nch);
        const int n1 = (c_begin + c + 1) * TK;

        if (have) {
            cp_async16(nsb + G1_P0 + psts0, gXh + n1);
            cp_async16(nsb + G1_P0 + psts1, gXh + n1 + 32);
            cp_async16(nsb + G1_P1 + psts0, gXl + n1);
            cp_async16(nsb + G1_P1 + psts1, gXl + n1 + 32);
            CP_COMMIT();
        }

        float4 pa[4];
        if (have) {
#pragma unroll
            for (int i = 0; i < 4; i++) {
                int n = n1 + i * 8 + w;
                pa[i] = (n < N_ && eok) ? *(const float4*)(H + (size_t)n * E_ + eA)
                                        : make_float4(0.f, 0.f, 0.f, 0.f);
            }
        }

        // ---- MMA pass p=0 (term-major) ----
        {
            uint32_t ah[2][4], al[2][4];
#pragma unroll
            for (int mt = 0; mt < 2; mt++) {
                uint32_t ao = sbo + abase + (uint32_t)(mt * 2048) + kpa[0];
                LDMX4(ah[mt], ao + G1_P0);
                LDMX4(al[mt], ao + G1_P1);
            }
            uint32_t bks = sbo + bbase + (uint32_t)(kg * 2 * 2048);
#pragma unroll
            for (int prq = 0; prq < 2; prq++) {
                uint32_t bh[2][4], bl[2][4];
#pragma unroll
                for (int pr2 = 0; pr2 < 2; pr2++) {
                    uint32_t bo = bks + (((uint32_t)((prq * 2 + pr2) * 32)) ^ m56);
                    LDMX4T(bh[pr2], bo + G1_Q0);
                    LDMX4T(bl[pr2], bo + G1_Q1);
                }
#pragma unroll
                for (int mt = 0; mt < 2; mt++)
#pragma unroll
                    for (int pr2 = 0; pr2 < 2; pr2++)
#pragma unroll
                        for (int sub = 0; sub < 2; sub++)
                            mma_bf16(acc[mt][(prq * 2 + pr2) * 2 + sub], ah[mt],
                                     bh[pr2][sub * 2], bh[pr2][sub * 2 + 1]);
#pragma unroll
                for (int mt = 0; mt < 2; mt++)
#pragma unroll
                    for (int pr2 = 0; pr2 < 2; pr2++)
#pragma unroll
                        for (int sub = 0; sub < 2; sub++)
                            mma_bf16(acc[mt][(prq * 2 + pr2) * 2 + sub], al[mt],
                                     bh[pr2][sub * 2], bh[pr2][sub * 2 + 1]);
#pragma unroll
                for (int mt = 0; mt < 2; mt++)
#pragma unroll
                    for (int pr2 = 0; pr2 < 2; pr2++)
#pragma unroll
                        for (int sub = 0; sub < 2; sub++)
                            mma_bf16(acc[mt][(prq * 2 + pr2) * 2 + sub], ah[mt],
                                     bl[pr2][sub * 2], bl[pr2][sub * 2 + 1]);
            }
        }

        if (have) {
#pragma unroll
            for (int i = 0; i < 4; i++) {
                uint2 hi, lo;
                cvt_pair(pa[i], hi, lo);
                uint32_t off = qsts + (uint32_t)(i * 1024);
                *(uint2*)(nbase + G1_Q0 + off) = hi;
                *(uint2*)(nbase + G1_Q1 + off) = lo;
            }
#pragma unroll
            for (int i = 0; i < 4; i++) {
                int n = n1 + (i + 4) * 8 + w;
                pa[i] = (n < N_ && eok) ? *(const float4*)(H + (size_t)n * E_ + eA)
                                        : make_float4(0.f, 0.f, 0.f, 0.f);
            }
        }

        // ---- MMA pass p=1 (term-major) ----
        {
            uint32_t ah[2][4], al[2][4];
#pragma unroll
            for (int mt = 0; mt < 2; mt++) {
                uint32_t ao = sbo + abase + (uint32_t)(mt * 2048) + kpa[1];
                LDMX4(ah[mt], ao + G1_P0);
                LDMX4(al[mt], ao + G1_P1);
            }
            uint32_t bks = sbo + bbase + (uint32_t)((kg * 2 + 1) * 2048);
#pragma unroll
            for (int prq = 0; prq < 2; prq++) {
                uint32_t bh[2][4], bl[2][4];
#pragma unroll
                for (int pr2 = 0; pr2 < 2; pr2++) {
                    uint32_t bo = bks + (((uint32_t)((prq * 2 + pr2) * 32)) ^ m56);
                    LDMX4T(bh[pr2], bo + G1_Q0);
                    LDMX4T(bl[pr2], bo + G1_Q1);
                }
#pragma unroll
                for (int mt = 0; mt < 2; mt++)
#pragma unroll
                    for (int pr2 = 0; pr2 < 2; pr2++)
#pragma unroll
                        for (int sub = 0; sub < 2; sub++)
                            mma_bf16(acc[mt][(prq * 2 + pr2) * 2 + sub], ah[mt],
                                     bh[pr2][sub * 2], bh[pr2][sub * 2 + 1]);
#pragma unroll
                for (int mt = 0; mt < 2; mt++)
#pragma unroll
                    for (int pr2 = 0; pr2 < 2; pr2++)
#pragma unroll
                        for (int sub = 0; sub < 2; sub++)
                            mma_bf16(acc[mt][(prq * 2 + pr2) * 2 + sub], al[mt],
                                     bh[pr2][sub * 2], bh[pr2][sub * 2 + 1]);
#pragma unroll
                for (int mt = 0; mt < 2; mt++)
#pragma unroll
                    for (int pr2 = 0; pr2 < 2; pr2++)
#pragma unroll
                        for (int sub = 0; sub < 2; sub++)
                            mma_bf16(acc[mt][(prq * 2 + pr2) * 2 + sub], ah[mt],
                                     bl[pr2][sub * 2], bl[pr2][sub * 2 + 1]);
            }
        }

        if (have) {
#pragma unroll
            for (int i = 0; i < 4; i++) {
                uint2 hi, lo;
                cvt_pair(pa[i], hi, lo);
                uint32_t off = qsts + (uint32_t)((i + 4) * 1024);
                *(uint2*)(nbase + G1_Q0 + off) = hi;
                *(uint2*)(nbase + G1_Q1 + off) = lo;
            }
        }
        CP_WAIT0();
        __syncthreads();
    }

    // epilogue: atomic accumulate into g_YT [f][e] (both k-groups add)
#pragma unroll
    for (int mt = 0; mt < 2; mt++) {
        int f = wf * 32 + mt * 16 + (lane >> 2);
#pragma unroll
        for (int q = 0; q < 8; q++) {
            int e = e0 + half * 64 + q * 8 + (lane & 3) * 2;
            if (e < E_) {
                atomicAdd(&g_YT[(size_t)f * E_ + e], acc[mt][q][0]);
                atomicAdd(&g_YT[(size_t)f * E_ + e + 1], acc[mt][q][1]);
                atomicAdd(&g_YT[(size_t)(f + 8) * E_ + e], acc[mt][q][2]);
                atomicAdd(&g_YT[(size_t)(f + 8) * E_ + e + 1], acc[mt][q][3]);
            }
        }
    }
}

// ============================================================================
// GEMM2: Z[N,64] += D_v^{-1/2} · H[N,E] · Yd
// 8 warps = 2 k-groups x (2 wn x 2 wfc). Warp tile 64n x 32f, 2 ks each.
// Term-major MMA ordering: same-acc reuse distance 8.
// ============================================================================
__global__ void __launch_bounds__(256, 2)
gemm2_kernel(const float* __restrict__ H, float* __restrict__ Z) {
    extern __shared__ char smem[];
    const uint32_t sb = smem_u32(smem);
    const int t = threadIdx.x;
    const int lane = t & 31, w = t >> 5;
    const int n0 = blockIdx.x * 128;
    const int c_begin = blockIdx.y * CPS2;
    int c_end = c_begin + CPS2;
    if (c_end > NCH2) c_end = NCH2;
    const int nch = c_end - c_begin;

    const int kg = w >> 2;
    const int wq = w & 3;
    const int wn = wq >> 1;         // 64-n half
    const int wfc = wq & 1;         // 32-f slice

    const uint32_t amask = (uint32_t)((lane & 7) << 4);
    const uint32_t a2base = (uint32_t)((wn * 64 + (lane & 15)) * 128);
    uint32_t kpa[2];
#pragma unroll
    for (int p = 0; p < 2; p++) {
        int ks = kg * 2 + p;
        kpa[p] = (uint32_t)(ks * 32 + (lane >> 4) * 16) ^ amask;
    }
    const uint32_t b2base = (uint32_t)((wfc * 32 + (lane >> 4) * 8 + (lane & 7)) * 128);
    uint32_t kpb[2];
#pragma unroll
    for (int p = 0; p < 2; p++) {
        int ks = kg * 2 + p;
        kpb[p] = (uint32_t)(ks * 32 + ((lane >> 3) & 1) * 16) ^ amask;
    }

    const int rb = w * 2 + (lane >> 4);
    const int kA = (lane & 15) * 4;
    const uint32_t a2sts = (uint32_t)(rb * 128 + (((lane & 15) * 8) ^ ((rb & 7) << 4)));
    const int fB = t >> 2, segB = t & 3;
    const uint32_t psts0 = SW128((uint32_t)(fB * 128 + segB * 16));
    const uint32_t psts1 = SW128((uint32_t)(fB * 128 + (segB + 4) * 16));
    const unsigned short* gYh = g_YdTh + (size_t)fB * E_ + segB * 8;
    const unsigned short* gYl = g_YdTl + (size_t)fB * E_ + segB * 8;

    float acc[4][4][4];
#pragma unroll
    for (int a = 0; a < 4; a++)
#pragma unroll
        for (int b = 0; b < 4; b++)
#pragma unroll
            for (int q = 0; q < 4; q++) acc[a][b][q] = 0.0f;

    // prologue: chunk 0 -> buf 0
    {
        const int k0 = c_begin * TK;
        cp_async16(sb + G2_B0 + psts0, gYh + k0);
        cp_async16(sb + G2_B0 + psts1, gYh + k0 + 32);
        cp_async16(sb + G2_B1 + psts0, gYl + k0);
        cp_async16(sb + G2_B1 + psts1, gYl + k0 + 32);
        CP_COMMIT();
#pragma unroll
        for (int g = 0; g < 2; g++) {
            float4 pa[4];
#pragma unroll
            for (int i = 0; i < 4; i++) {
                int n = n0 + (g * 4 + i) * 16 + rb;
                pa[i] = (n < N_) ? *(const float4*)(H + (size_t)n * E_ + k0 + kA)
                                 : make_float4(0.f, 0.f, 0.f, 0.f);
            }
#pragma unroll
            for (int i = 0; i < 4; i++) {
                uint2 hi, lo;
                cvt_pair(pa[i], hi, lo);
                uint32_t off = a2sts + (uint32_t)((g * 4 + i) * 2048);
                *(uint2*)(smem + G2_A0 + off) = hi;
                *(uint2*)(smem + G2_A1 + off) = lo;
            }
        }
        CP_WAIT0();
    }
    __syncthreads();

    for (int c = 0; c < nch; c++) {
        const int buf = c & 1;
        const uint32_t sbo = sb + buf * STAGE;
        char* nbase = smem + (buf ^ 1) * STAGE;
        const uint32_t nsb = sb + (buf ^ 1) * STAGE;
        const bool have = (c + 1 < nch);
        const int k1 = (c_begin + c + 1) * TK;

        if (have) {
            cp_async16(nsb + G2_B0 + psts0, gYh + k1);
            cp_async16(nsb + G2_B0 + psts1, gYh + k1 + 32);
            cp_async16(nsb + G2_B1 + psts0, gYl + k1);
            cp_async16(nsb + G2_B1 + psts1, gYl + k1 + 32);
            CP_COMMIT();
        }

        float4 pa[4];
        if (have) {
#pragma unroll
            for (int i = 0; i < 4; i++) {
                int n = n0 + i * 16 + rb;
                pa[i] = (n < N_) ? *(const float4*)(H + (size_t)n * E_ + k1 + kA)
                                 : make_float4(0.f, 0.f, 0.f, 0.f);
            }
        }

        // ---- MMA pass p=0 (term-major) ----
        {
            uint32_t bh[2][4], bl[2][4];
#pragma unroll
            for (int nt = 0; nt < 2; nt++) {
                uint32_t bo = sbo + b2base + (uint32_t)(nt * 2048) + kpb[0];
                LDMX4(bh[nt], bo + G2_B0);
                LDMX4(bl[nt], bo + G2_B1);
            }
#pragma unroll
            for (int mg = 0; mg < 2; mg++) {
                uint32_t ah[2][4], al[2][4];
#pragma unroll
                for (int mi = 0; mi < 2; mi++) {
                    uint32_t ao = sbo + a2base + (uint32_t)((mg * 2 + mi) * 2048) + kpa[0];
                    LDMX4(ah[mi], ao + G2_A0);
                    LDMX4(al[mi], ao + G2_A1);
                }
#pragma unroll
                for (int mi = 0; mi < 2; mi++)
#pragma unroll
                    for (int nt = 0; nt < 2; nt++)
#pragma unroll
                        for (int sub = 0; sub < 2; sub++)
                            mma_bf16(acc[mg * 2 + mi][nt * 2 + sub], ah[mi],
                                     bh[nt][sub * 2], bh[nt][sub * 2 + 1]);
#pragma unroll
                for (int mi = 0; mi < 2; mi++)
#pragma unroll
                    for (int nt = 0; nt < 2; nt++)
#pragma unroll
                        for (int sub = 0; sub < 2; sub++)
                            mma_bf16(acc[mg * 2 + mi][nt * 2 + sub], al[mi],
                                     bh[nt][sub * 2], bh[nt][sub * 2 + 1]);
#pragma unroll
                for (int mi = 0; mi < 2; mi++)
#pragma unroll
                    for (int nt = 0; nt < 2; nt++)
#pragma unroll
                        for (int sub = 0; sub < 2; sub++)
                            mma_bf16(acc[mg * 2 + mi][nt * 2 + sub], ah[mi],
                                     bl[nt][sub * 2], bl[nt][sub * 2 + 1]);
            }
        }

        if (have) {
#pragma unroll
            for (int i = 0; i < 4; i++) {
                uint2 hi, lo;
                cvt_pair(pa[i], hi, lo);
                uint32_t off = a2sts + (uint32_t)(i * 2048);
                *(uint2*)(nbase + G2_A0 + off) = hi;
                *(uint2*)(nbase + G2_A1 + off) = lo;
            }
#pragma unroll
            for (int i = 0; i < 4; i++) {
                int n = n0 + (i + 4) * 16 + rb;
                pa[i] = (n < N_) ? *(const float4*)(H + (size_t)n * E_ + k1 + kA)
                                 : make_float4(0.f, 0.f, 0.f, 0.f);
            }
        }

        // ---- MMA pass p=1 (term-major) ----
        {
            uint32_t bh[2][4], bl[2][4];
#pragma unroll
            for (int nt = 0; nt < 2; nt++) {
                uint32_t bo = sbo + b2base + (uint32_t)(nt * 2048) + kpb[1];
                LDMX4(bh[nt], bo + G2_B0);
                LDMX4(bl[nt], bo + G2_B1);
            }
#pragma unroll
            for (int mg = 0; mg < 2; mg++) {
                uint32_t ah[2][4], al[2][4];
#pragma unroll
                for (int mi = 0; mi < 2; mi++) {
                    uint32_t ao = sbo + a2base + (uint32_t)((mg * 2 + mi) * 2048) + kpa[1];
                    LDMX4(ah[mi], ao + G2_A0);
                    LDMX4(al[mi], ao + G2_A1);
                }
#pragma unroll
                for (int mi = 0; mi < 2; mi++)
#pragma unroll
                    for (int nt = 0; nt < 2; nt++)
#pragma unroll
                        for (int sub = 0; sub < 2; sub++)
                            mma_bf16(acc[mg * 2 + mi][nt * 2 + sub], ah[mi],
                                     bh[nt][sub * 2], bh[nt][sub * 2 + 1]);
#pragma unroll
                for (int mi = 0; mi < 2; mi++)
#pragma unroll
                    for (int nt = 0; nt < 2; nt++)
#pragma unroll
                        for (int sub = 0; sub < 2; sub++)
                            mma_bf16(acc[mg * 2 + mi][nt * 2 + sub], al[mi],
                                     bh[nt][sub * 2], bh[nt][sub * 2 + 1]);
#pragma unroll
                for (int mi = 0; mi < 2; mi++)
#pragma unroll
                    for (int nt = 0; nt < 2; nt++)
#pragma unroll
                        for (int sub = 0; sub < 2; sub++)
                            mma_bf16(acc[mg * 2 + mi][nt * 2 + sub], ah[mi],
                                     bl[nt][sub * 2], bl[nt][sub * 2 + 1]);
            }
        }

        if (have) {
#pragma unroll
            for (int i = 0; i < 4; i++) {
                uint2 hi, lo;
                cvt_pair(pa[i], hi, lo);
                uint32_t off = a2sts + (uint32_t)((i + 4) * 2048);
                *(uint2*)(nbase + G2_A0 + off) = hi;
                *(uint2*)(nbase + G2_A1 + off) = lo;
            }
        }
        CP_WAIT0();
        __syncthreads();
    }

    // epilogue: scale partials by rsqrt(d_v) and atomically accumulate
#pragma unroll
    for (int mt = 0; mt < 4; mt++) {
        int n_lo = n0 + wn * 64 + mt * 16 + (lane >> 2);
        int n_hi = n_lo + 8;
        float s_lo = (n_lo < N_) ? rsqrtf(g_dv[n_lo] + EPS) : 0.0f;
        float s_hi = (n_hi < N_) ? rsqrtf(g_dv[n_hi] + EPS) : 0.0f;
#pragma unroll
        for (int q = 0; q < 4; q++) {
            int f = wfc * 32 + q * 8 + (lane & 3) * 2;
            if (n_lo < N_) {
                atomicAdd(&Z[(size_t)n_lo * 64 + f], acc[mt][q][0] * s_lo);
                atomicAdd(&Z[(size_t)n_lo * 64 + f + 1], acc[mt][q][1] * s_lo);
            }
            if (n_hi < N_) {
                atomicAdd(&Z[(size_t)n_hi * 64 + f], acc[mt][q][2] * s_hi);
                atomicAdd(&Z[(size_t)n_hi * 64 + f + 1], acc[mt][q][3] * s_hi);
            }
        }
    }
}

// ---------------------------------------------------------------------------
extern "C" void kernel_launch(void* const* d_in, const int* in_sizes, int n_in,
                              void* d_out, int out_size) {
    const float* H = (const float*)d_in[0];  // [N_, E_] fp32
    const float* X = (const float*)d_in[1];  // [N_, F_] fp32
    float* Z = (float*)d_out;                // [N_, F_] fp32

    cudaFuncSetAttribute(gemm1_kernel, cudaFuncAttributeMaxDynamicSharedMemorySize, G_TOTAL);
    cudaFuncSetAttribute(gemm2_kernel, cudaFuncAttributeMaxDynamicSharedMemorySize, G_TOTAL);

    zero_scratch<<<(N_ * F_ + 255) / 256, 256>>>(Z);
    degrees_kernel<<<444, 256>>>(H);
    scale_x_t<<<(NPAD + 127) / 128, 256>>>(X);
    gemm1_kernel<<<dim3(ETILES1, SPLIT1), 256, G_TOTAL>>>(H);
    scale_y_t<<<(64 * E_ + 255) / 256, 256>>>();
    gemm2_kernel<<<dim3(NTILES2, SPLIT2), 256, G_TOTAL>>>(H, Z);
}

// round 13
// speedup vs baseline: 2.1312x; 1.3005x over previous
#include <cuda_runtime.h>
#include <cuda_bf16.h>
#include <cuda_fp16.h>
#include <cstdint>

#define N_ 20000
#define E_ 8000
#define F_ 64
#define EPS 1e-10f

#define NPAD 20032          // N_ padded to multiple of 64
#define TK 64               // K elements per chunk
#define NCH1 313            // NPAD/64
#define SPLIT1 9
#define CPS1 35             // ceil(313/9)
#define ETILES1 63          // ceil(E_/128)
#define NCH2 125            // E_/64
#define SPLIT2 3
#define CPS2 42             // ceil(125/3)
#define NTILES2 157         // ceil(N_/128)

// gemm1 per-stage: P 8K (XsT fp16) | Q 16K (H fp16, two 8K e-halves)
#define G1_P0 0
#define G1_Q0 8192
// gemm2 per-stage: A 16K (H fp16) | B 8K (YdT fp16)
#define G2_A0 0
#define G2_B0 16384
#define STAGE 24576
#define G_TOTAL (2 * STAGE)   // 49152 -> 2 CTAs/SM (reg-limited)

// ---------------- scratch ----------------
__device__ float g_dv[N_];
__device__ float g_de[E_];
__device__ float g_YT[64 * E_];            // Y^T [f][e]
__device__ unsigned short g_XsTf[64 * NPAD];   // fp16
__device__ unsigned short g_YdTf[64 * E_];     // fp16 [f][e]

// ---------------- helpers ----------------
__device__ __forceinline__ uint32_t smem_u32(const void* p) {
    uint32_t a;
    asm("{ .reg .u64 tmp; cvta.to.shared.u64 tmp, %1; cvt.u32.u64 %0, tmp; }"
        : "=r"(a) : "l"(p));
    return a;
}
#define SW128(o) ((uint32_t)(o) ^ (((uint32_t)(o) >> 3) & 0x70))

__device__ __forceinline__ uint2 cvt_h4(float4 v) {
    __half2 a = __floats2half2_rn(v.x, v.y);
    __half2 b = __floats2half2_rn(v.z, v.w);
    return make_uint2(*(uint32_t*)&a, *(uint32_t*)&b);
}

#define LDMX4(r, addr) \
    asm volatile("ldmatrix.sync.aligned.m8n8.x4.shared.b16 {%0,%1,%2,%3}, [%4];" \
        : "=r"((r)[0]), "=r"((r)[1]), "=r"((r)[2]), "=r"((r)[3]) : "r"(addr))
#define LDMX4T(r, addr) \
    asm volatile("ldmatrix.sync.aligned.m8n8.x4.trans.shared.b16 {%0,%1,%2,%3}, [%4];" \
        : "=r"((r)[0]), "=r"((r)[1]), "=r"((r)[2]), "=r"((r)[3]) : "r"(addr))

__device__ __forceinline__ void mma_f16(float* c, const uint32_t* a,
                                        uint32_t b0, uint32_t b1) {
    asm volatile(
        "mma.sync.aligned.m16n8k16.row.col.f32.f16.f16.f32 "
        "{%0,%1,%2,%3}, {%4,%5,%6,%7}, {%8,%9}, {%0,%1,%2,%3};"
        : "+f"(c[0]), "+f"(c[1]), "+f"(c[2]), "+f"(c[3])
        : "r"(a[0]), "r"(a[1]), "r"(a[2]), "r"(a[3]), "r"(b0), "r"(b1));
}

__device__ __forceinline__ void cp_async16(uint32_t dst, const void* src) {
    asm volatile("cp.async.cg.shared.global [%0], [%1], 16;"
                 :: "r"(dst), "l"(src) : "memory");
}
#define CP_COMMIT() asm volatile("cp.async.commit_group;" ::: "memory")
#define CP_WAIT0()  asm volatile("cp.async.wait_group 0;" ::: "memory")

// ---------------- zero scratch (incl. output) ----------------
__global__ void zero_scratch(float* __restrict__ Z) {
    int i = blockIdx.x * blockDim.x + threadIdx.x;
    if (i < N_ * F_) Z[i] = 0.0f;
    if (i < 64 * E_) g_YT[i] = 0.0f;
    if (i < E_) g_de[i] = 0.0f;
}

// ---------------- degrees (one pass over H) ----------------
__global__ void __launch_bounds__(256) degrees_kernel(const float* __restrict__ H) {
    const int t = threadIdx.x;
    const int r0 = blockIdx.x * 46;
    const int r1 = (r0 + 46 < N_) ? r0 + 46 : N_;

    float de_acc[32];
#pragma unroll
    for (int j = 0; j < 32; j++) de_acc[j] = 0.0f;

    __shared__ float wsum[8];

    for (int r = r0; r < r1; r++) {
        const float* __restrict__ row = H + (size_t)r * E_;
        float rs = 0.0f;
#pragma unroll
        for (int j = 0; j < 32; j++) {
            int c = t + 256 * j;
            if (c < E_) {
                float v = row[c];
                rs += v;
                de_acc[j] += v;
            }
        }
#pragma unroll
        for (int off = 16; off > 0; off >>= 1)
            rs += __shfl_down_sync(0xffffffffu, rs, off);
        if ((t & 31) == 0) wsum[t >> 5] = rs;
        __syncthreads();
        if (t == 0) {
            float s = 0.0f;
#pragma unroll
            for (int w = 0; w < 8; w++) s += wsum[w];
            g_dv[r] = s;
        }
        __syncthreads();
    }
#pragma unroll
    for (int j = 0; j < 32; j++) {
        int c = t + 256 * j;
        if (c < E_) atomicAdd(&g_de[c], de_acc[j]);
    }
}

// ---------------- Xs^T materialization (scaled, fp16, transposed) ----------
__global__ void __launch_bounds__(256) scale_x_t(const float* __restrict__ X) {
    __shared__ unsigned short sh[64 * 130];
    const int t = threadIdx.x;
    const int n0 = blockIdx.x * 128;
#pragma unroll
    for (int i = 0; i < 32; i++) {
        int idx = i * 256 + t;
        int nl = idx >> 6, f = idx & 63;
        int n = n0 + nl;
        float v = 0.0f;
        if (n < N_) v = X[(size_t)n * 64 + f] * rsqrtf(g_dv[n] + EPS);
        __half hv = __float2half_rn(v);
        sh[f * 130 + nl] = *(unsigned short*)&hv;
    }
    __syncthreads();
#pragma unroll
    for (int i = 0; i < 32; i++) {
        int idx = i * 256 + t;
        int f = idx >> 7, nl = idx & 127;
        int n = n0 + nl;
        if (n < NPAD) g_XsTf[(size_t)f * NPAD + n] = sh[f * 130 + nl];
    }
}

// ---------------- Yd^T: elementwise scale -> fp16 (f-major) ----------------
__global__ void __launch_bounds__(256) scale_y_t() {
    int i = blockIdx.x * blockDim.x + threadIdx.x;
    if (i < 64 * E_) {
        int e = i % E_;
        float v = g_YT[i] * (1.0f / (g_de[e] + EPS));
        __half hv = __float2half_rn(v);
        g_YdTf[i] = *(unsigned short*)&hv;
    }
}

// ============================================================================
// GEMM1: Y^T[64 f, E] += Xs^T[64 f, N] · H[N, E]   (single-term fp16)
// 8 warps = 2 k-groups x (2 wf x 2 e-half). Warp tile 32f x 64e, 2 ks each.
// ============================================================================
__global__ void __launch_bounds__(256, 2)
gemm1_kernel(const float* __restrict__ H) {
    extern __shared__ char smem[];
    const uint32_t sb = smem_u32(smem);
    const int t = threadIdx.x;
    const int lane = t & 31, w = t >> 5;
    const int e0 = blockIdx.x * 128;
    const int c_begin = blockIdx.y * CPS1;
    int c_end = c_begin + CPS1;
    if (c_end > NCH1) c_end = NCH1;
    const int nch = c_end - c_begin;

    const int kg = w >> 2;          // ks = kg*2 + {0,1}
    const int wq = w & 3;
    const int wf = wq & 1;          // 32-f slice
    const int half = wq >> 1;       // 64-e half

    const uint32_t amask = (uint32_t)((lane & 7) << 4);
    const uint32_t abase = (uint32_t)((wf * 32 + (lane & 15)) * 128);
    uint32_t kpa[2];
#pragma unroll
    for (int p = 0; p < 2; p++) {
        int ks = kg * 2 + p;
        kpa[p] = (uint32_t)(ks * 32 + (lane >> 4) * 16) ^ amask;
    }
    const int gq = lane >> 3, jj = lane & 7;
    const uint32_t m56 = (uint32_t)((jj << 4) & 96);
    const uint32_t bbase = (uint32_t)(half * 8192 + ((gq & 1) * 8 + jj) * 128 +
                                      (((gq >> 1) * 16) ^ ((jj << 4) & 16)));

    const int eA = e0 + lane * 4;
    const bool eok = (eA < E_);
    const uint32_t qsts = (uint32_t)((lane >> 4) * 8192 +
                          ((w * 128 + (lane & 15) * 8) ^ (w << 4)));
    const int fB = t >> 2, segB = t & 3;
    const uint32_t psts0 = SW128((uint32_t)(fB * 128 + segB * 16));
    const uint32_t psts1 = SW128((uint32_t)(fB * 128 + (segB + 4) * 16));
    const unsigned short* gXf = g_XsTf + (size_t)fB * NPAD + segB * 8;

    float acc[2][8][4];
#pragma unroll
    for (int a = 0; a < 2; a++)
#pragma unroll
        for (int b = 0; b < 8; b++)
#pragma unroll
            for (int q = 0; q < 4; q++) acc[a][b][q] = 0.0f;

    // prologue: chunk 0 -> buf 0
    {
        const int n0 = c_begin * TK;
        cp_async16(sb + G1_P0 + psts0, gXf + n0);
        cp_async16(sb + G1_P0 + psts1, gXf + n0 + 32);
        CP_COMMIT();
#pragma unroll
        for (int g = 0; g < 2; g++) {
            float4 pa[4];
#pragma unroll
            for (int i = 0; i < 4; i++) {
                int n = n0 + (g * 4 + i) * 8 + w;
                pa[i] = (n < N_ && eok) ? *(const float4*)(H + (size_t)n * E_ + eA)
                                        : make_float4(0.f, 0.f, 0.f, 0.f);
            }
#pragma unroll
            for (int i = 0; i < 4; i++) {
                uint32_t off = qsts + (uint32_t)((g * 4 + i) * 1024);
                *(uint2*)(smem + G1_Q0 + off) = cvt_h4(pa[i]);
            }
        }
        CP_WAIT0();
    }
    __syncthreads();

    for (int c = 0; c < nch; c++) {
        const int buf = c & 1;
        const uint32_t sbo = sb + buf * STAGE;
        char* nbase = smem + (buf ^ 1) * STAGE;
        const uint32_t nsb = sb + (buf ^ 1) * STAGE;
        const bool have = (c + 1 < nch);
        const int n1 = (c_begin + c + 1) * TK;

        if (have) {
            cp_async16(nsb + G1_P0 + psts0, gXf + n1);
            cp_async16(nsb + G1_P0 + psts1, gXf + n1 + 32);
            CP_COMMIT();
        }

        float4 pa[4];
        if (have) {
#pragma unroll
            for (int i = 0; i < 4; i++) {
                int n = n1 + i * 8 + w;
                pa[i] = (n < N_ && eok) ? *(const float4*)(H + (size_t)n * E_ + eA)
                                        : make_float4(0.f, 0.f, 0.f, 0.f);
            }
        }

        // ---- MMA pass p=0 ----
        {
            uint32_t ah[2][4];
#pragma unroll
            for (int mt = 0; mt < 2; mt++)
                LDMX4(ah[mt], sbo + G1_P0 + abase + (uint32_t)(mt * 2048) + kpa[0]);
            uint32_t bks = sbo + bbase + (uint32_t)(kg * 2 * 2048);
#pragma unroll
            for (int prq = 0; prq < 2; prq++) {
                uint32_t bh[2][4];
#pragma unroll
                for (int pr2 = 0; pr2 < 2; pr2++)
                    LDMX4T(bh[pr2],
                           bks + (((uint32_t)((prq * 2 + pr2) * 32)) ^ m56) + G1_Q0);
#pragma unroll
                for (int mt = 0; mt < 2; mt++)
#pragma unroll
                    for (int pr2 = 0; pr2 < 2; pr2++)
#pragma unroll
                        for (int sub = 0; sub < 2; sub++)
                            mma_f16(acc[mt][(prq * 2 + pr2) * 2 + sub], ah[mt],
                                    bh[pr2][sub * 2], bh[pr2][sub * 2 + 1]);
            }
        }

        if (have) {
#pragma unroll
            for (int i = 0; i < 4; i++) {
                uint32_t off = qsts + (uint32_t)(i * 1024);
                *(uint2*)(nbase + G1_Q0 + off) = cvt_h4(pa[i]);
            }
#pragma unroll
            for (int i = 0; i < 4; i++) {
                int n = n1 + (i + 4) * 8 + w;
                pa[i] = (n < N_ && eok) ? *(const float4*)(H + (size_t)n * E_ + eA)
                                        : make_float4(0.f, 0.f, 0.f, 0.f);
            }
        }

        // ---- MMA pass p=1 ----
        {
            uint32_t ah[2][4];
#pragma unroll
            for (int mt = 0; mt < 2; mt++)
                LDMX4(ah[mt], sbo + G1_P0 + abase + (uint32_t)(mt * 2048) + kpa[1]);
            uint32_t bks = sbo + bbase + (uint32_t)((kg * 2 + 1) * 2048);
#pragma unroll
            for (int prq = 0; prq < 2; prq++) {
                uint32_t bh[2][4];
#pragma unroll
                for (int pr2 = 0; pr2 < 2; pr2++)
                    LDMX4T(bh[pr2],
                           bks + (((uint32_t)((prq * 2 + pr2) * 32)) ^ m56) + G1_Q0);
#pragma unroll
                for (int mt = 0; mt < 2; mt++)
#pragma unroll
                    for (int pr2 = 0; pr2 < 2; pr2++)
#pragma unroll
                        for (int sub = 0; sub < 2; sub++)
                            mma_f16(acc[mt][(prq * 2 + pr2) * 2 + sub], ah[mt],
                                    bh[pr2][sub * 2], bh[pr2][sub * 2 + 1]);
            }
        }

        if (have) {
#pragma unroll
            for (int i = 0; i < 4; i++) {
                uint32_t off = qsts + (uint32_t)((i + 4) * 1024);
                *(uint2*)(nbase + G1_Q0 + off) = cvt_h4(pa[i]);
            }
        }
        CP_WAIT0();
        __syncthreads();
    }

    // epilogue: atomic accumulate into g_YT [f][e] (both k-groups add)
#pragma unroll
    for (int mt = 0; mt < 2; mt++) {
        int f = wf * 32 + mt * 16 + (lane >> 2);
#pragma unroll
        for (int q = 0; q < 8; q++) {
            int e = e0 + half * 64 + q * 8 + (lane & 3) * 2;
            if (e < E_) {
                atomicAdd(&g_YT[(size_t)f * E_ + e], acc[mt][q][0]);
                atomicAdd(&g_YT[(size_t)f * E_ + e + 1], acc[mt][q][1]);
                atomicAdd(&g_YT[(size_t)(f + 8) * E_ + e], acc[mt][q][2]);
                atomicAdd(&g_YT[(size_t)(f + 8) * E_ + e + 1], acc[mt][q][3]);
            }
        }
    }
}

// ============================================================================
// GEMM2: Z[N,64] += D_v^{-1/2} · H[N,E] · Yd   (single-term fp16)
// 8 warps = 2 k-groups x (2 wn x 2 wfc). Warp tile 64n x 32f, 2 ks each.
// ============================================================================
__global__ void __launch_bounds__(256, 2)
gemm2_kernel(const float* __restrict__ H, float* __restrict__ Z) {
    extern __shared__ char smem[];
    const uint32_t sb = smem_u32(smem);
    const int t = threadIdx.x;
    const int lane = t & 31, w = t >> 5;
    const int n0 = blockIdx.x * 128;
    const int c_begin = blockIdx.y * CPS2;
    int c_end = c_begin + CPS2;
    if (c_end > NCH2) c_end = NCH2;
    const int nch = c_end - c_begin;

    const int kg = w >> 2;
    const int wq = w & 3;
    const int wn = wq >> 1;         // 64-n half
    const int wfc = wq & 1;         // 32-f slice

    const uint32_t amask = (uint32_t)((lane & 7) << 4);
    const uint32_t a2base = (uint32_t)((wn * 64 + (lane & 15)) * 128);
    uint32_t kpa[2];
#pragma unroll
    for (int p = 0; p < 2; p++) {
        int ks = kg * 2 + p;
        kpa[p] = (uint32_t)(ks * 32 + (lane >> 4) * 16) ^ amask;
    }
    const uint32_t b2base = (uint32_t)((wfc * 32 + (lane >> 4) * 8 + (lane & 7)) * 128);
    uint32_t kpb[2];
#pragma unroll
    for (int p = 0; p < 2; p++) {
        int ks = kg * 2 + p;
        kpb[p] = (uint32_t)(ks * 32 + ((lane >> 3) & 1) * 16) ^ amask;
    }

    const int rb = w * 2 + (lane >> 4);
    const int kA = (lane & 15) * 4;
    const uint32_t a2sts = (uint32_t)(rb * 128 + (((lane & 15) * 8) ^ ((rb & 7) << 4)));
    const int fB = t >> 2, segB = t & 3;
    const uint32_t psts0 = SW128((uint32_t)(fB * 128 + segB * 16));
    const uint32_t psts1 = SW128((uint32_t)(fB * 128 + (segB + 4) * 16));
    const unsigned short* gYf = g_YdTf + (size_t)fB * E_ + segB * 8;

    float acc[4][4][4];
#pragma unroll
    for (int a = 0; a < 4; a++)
#pragma unroll
        for (int b = 0; b < 4; b++)
#pragma unroll
            for (int q = 0; q < 4; q++) acc[a][b][q] = 0.0f;

    // prologue: chunk 0 -> buf 0
    {
        const int k0 = c_begin * TK;
        cp_async16(sb + G2_B0 + psts0, gYf + k0);
        cp_async16(sb + G2_B0 + psts1, gYf + k0 + 32);
        CP_COMMIT();
#pragma unroll
        for (int g = 0; g < 2; g++) {
            float4 pa[4];
#pragma unroll
            for (int i = 0; i < 4; i++) {
                int n = n0 + (g * 4 + i) * 16 + rb;
                pa[i] = (n < N_) ? *(const float4*)(H + (size_t)n * E_ + k0 + kA)
                                 : make_float4(0.f, 0.f, 0.f, 0.f);
            }
#pragma unroll
            for (int i = 0; i < 4; i++) {
                uint32_t off = a2sts + (uint32_t)((g * 4 + i) * 2048);
                *(uint2*)(smem + G2_A0 + off) = cvt_h4(pa[i]);
            }
        }
        CP_WAIT0();
    }
    __syncthreads();

    for (int c = 0; c < nch; c++) {
        const int buf = c & 1;
        const uint32_t sbo = sb + buf * STAGE;
        char* nbase = smem + (buf ^ 1) * STAGE;
        const uint32_t nsb = sb + (buf ^ 1) * STAGE;
        const bool have = (c + 1 < nch);
        const int k1 = (c_begin + c + 1) * TK;

        if (have) {
            cp_async16(nsb + G2_B0 + psts0, gYf + k1);
            cp_async16(nsb + G2_B0 + psts1, gYf + k1 + 32);
            CP_COMMIT();
        }

        float4 pa[4];
        if (have) {
#pragma unroll
            for (int i = 0; i < 4; i++) {
                int n = n0 + i * 16 + rb;
                pa[i] = (n < N_) ? *(const float4*)(H + (size_t)n * E_ + k1 + kA)
                                 : make_float4(0.f, 0.f, 0.f, 0.f);
            }
        }

        // ---- MMA pass p=0 ----
        {
            uint32_t bh[2][4];
#pragma unroll
            for (int nt = 0; nt < 2; nt++)
                LDMX4(bh[nt], sbo + G2_B0 + b2base + (uint32_t)(nt * 2048) + kpb[0]);
#pragma unroll
            for (int mg = 0; mg < 2; mg++) {
                uint32_t ah[2][4];
#pragma unroll
                for (int mi = 0; mi < 2; mi++)
                    LDMX4(ah[mi], sbo + G2_A0 + a2base +
                                  (uint32_t)((mg * 2 + mi) * 2048) + kpa[0]);
#pragma unroll
                for (int mi = 0; mi < 2; mi++)
#pragma unroll
                    for (int nt = 0; nt < 2; nt++)
#pragma unroll
                        for (int sub = 0; sub < 2; sub++)
                            mma_f16(acc[mg * 2 + mi][nt * 2 + sub], ah[mi],
                                    bh[nt][sub * 2], bh[nt][sub * 2 + 1]);
            }
        }

        if (have) {
#pragma unroll
            for (int i = 0; i < 4; i++) {
                uint32_t off = a2sts + (uint32_t)(i * 2048);
                *(uint2*)(nbase + G2_A0 + off) = cvt_h4(pa[i]);
            }
#pragma unroll
            for (int i = 0; i < 4; i++) {
                int n = n0 + (i + 4) * 16 + rb;
                pa[i] = (n < N_) ? *(const float4*)(H + (size_t)n * E_ + k1 + kA)
                                 : make_float4(0.f, 0.f, 0.f, 0.f);
            }
        }

        // ---- MMA pass p=1 ----
        {
            uint32_t bh[2][4];
#pragma unroll
            for (int nt = 0; nt < 2; nt++)
                LDMX4(bh[nt], sbo + G2_B0 + b2base + (uint32_t)(nt * 2048) + kpb[1]);
#pragma unroll
            for (int mg = 0; mg < 2; mg++) {
                uint32_t ah[2][4];
#pragma unroll
                for (int mi = 0; mi < 2; mi++)
                    LDMX4(ah[mi], sbo + G2_A0 + a2base +
                                  (uint32_t)((mg * 2 + mi) * 2048) + kpa[1]);
#pragma unroll
                for (int mi = 0; mi < 2; mi++)
#pragma unroll
                    for (int nt = 0; nt < 2; nt++)
#pragma unroll
                        for (int sub = 0; sub < 2; sub++)
                            mma_f16(acc[mg * 2 + mi][nt * 2 + sub], ah[mi],
                                    bh[nt][sub * 2], bh[nt][sub * 2 + 1]);
            }
        }

        if (have) {
#pragma unroll
            for (int i = 0; i < 4; i++) {
                uint32_t off = a2sts + (uint32_t)((i + 4) * 2048);
                *(uint2*)(nbase + G2_A0 + off) = cvt_h4(pa[i]);
            }
        }
        CP_WAIT0();
        __syncthreads();
    }

    // epilogue: scale partials by rsqrt(d_v) and atomically accumulate
#pragma unroll
    for (int mt = 0; mt < 4; mt++) {
        int n_lo = n0 + wn * 64 + mt * 16 + (lane >> 2);
        int n_hi = n_lo + 8;
        float s_lo = (n_lo < N_) ? rsqrtf(g_dv[n_lo] + EPS) : 0.0f;
        float s_hi = (n_hi < N_) ? rsqrtf(g_dv[n_hi] + EPS) : 0.0f;
#pragma unroll
        for (int q = 0; q < 4; q++) {
            int f = wfc * 32 + q * 8 + (lane & 3) * 2;
            if (n_lo < N_) {
                atomicAdd(&Z[(size_t)n_lo * 64 + f], acc[mt][q][0] * s_lo);
                atomicAdd(&Z[(size_t)n_lo * 64 + f + 1], acc[mt][q][1] * s_lo);
            }
            if (n_hi < N_) {
                atomicAdd(&Z[(size_t)n_hi * 64 + f], acc[mt][q][2] * s_hi);
                atomicAdd(&Z[(size_t)n_hi * 64 + f + 1], acc[mt][q][3] * s_hi);
            }
        }
    }
}

// ---------------------------------------------------------------------------
extern "C" void kernel_launch(void* const* d_in, const int* in_sizes, int n_in,
                              void* d_out, int out_size) {
    const float* H = (const float*)d_in[0];  // [N_, E_] fp32
    const float* X = (const float*)d_in[1];  // [N_, F_] fp32
    float* Z = (float*)d_out;                // [N_, F_] fp32

    cudaFuncSetAttribute(gemm1_kernel, cudaFuncAttributeMaxDynamicSharedMemorySize, G_TOTAL);
    cudaFuncSetAttribute(gemm2_kernel, cudaFuncAttributeMaxDynamicSharedMemorySize, G_TOTAL);

    zero_scratch<<<(N_ * F_ + 255) / 256, 256>>>(Z);
    degrees_kernel<<<444, 256>>>(H);
    scale_x_t<<<(NPAD + 127) / 128, 256>>>(X);
    gemm1_kernel<<<dim3(ETILES1, SPLIT1), 256, G_TOTAL>>>(H);
    scale_y_t<<<(64 * E_ + 255) / 256, 256>>>();
    gemm2_kernel<<<dim3(NTILES2, SPLIT2), 256, G_TOTAL>>>(H, Z);
}